// round 14
// baseline (speedup 1.0000x reference)
#include <cuda_runtime.h>
#include <cuda_bf16.h>
#include <cuda_fp16.h>
#include <stdint.h>

#define Bd  8
#define Ld  2016
#define Hd  4
#define DKd 32
#define Dd  256
#define FCd 64
#define NLd 3
#define BLd (Bd*Ld)          // 16128 tokens

#define SC2f 0.09016844005556f   // (1/sqrt(256)) * log2(e)
#define EPSLN 1e-5f

// ---------------------------------------------------------------------------
// Device scratch. Residual stream: split fp16 only (fp32 dropped; hi+lo is
// exact to 2^-21 relative). Weights: fp16.
// ---------------------------------------------------------------------------
__device__ __align__(128) __half  g_hh   [BLd*Dd];
__device__ __align__(128) __half  g_hl   [BLd*Dd];
__device__ __align__(128) __half  g_qkv  [3*BLd*128];   // fp16 (Q pre-scaled)
__device__ __align__(128) __half  g_oh   [BLd*128];
__device__ __align__(128) __half  g_ol   [BLd*128];
__device__ __align__(128) float   g_tmp  [BLd*Dd];
__device__ __align__(128) __half  g_fh   [BLd*FCd];
__device__ __align__(128) __half  g_fl   [BLd*FCd];
// fp16 weights
__device__ __align__(128) __half  g_qkvw [NLd*3*Dd*128];
__device__ __align__(128) float   g_qkvb [NLd*3*128];
__device__ __align__(128) __half  g_ow   [NLd*128*Dd];
__device__ __align__(128) __half  g_f1w  [NLd*Dd*FCd];
__device__ __align__(128) __half  g_f2w  [NLd*FCd*Dd];
__device__ __align__(128) __half  g_o1w  [Dd*Dd];

// ---------------------------------------------------------------------------
// helpers
// ---------------------------------------------------------------------------
__device__ __forceinline__ void mma16816h(float* d, const uint32_t* a,
                                          uint32_t b0, uint32_t b1) {
    asm volatile(
        "mma.sync.aligned.m16n8k16.row.col.f32.f16.f16.f32 "
        "{%0,%1,%2,%3}, {%4,%5,%6,%7}, {%8,%9}, {%0,%1,%2,%3};"
        : "+f"(d[0]), "+f"(d[1]), "+f"(d[2]), "+f"(d[3])
        : "r"(a[0]), "r"(a[1]), "r"(a[2]), "r"(a[3]), "r"(b0), "r"(b1));
}

__device__ __forceinline__ void ldsm4(uint32_t& r0, uint32_t& r1,
                                      uint32_t& r2, uint32_t& r3, uint32_t a) {
    asm volatile("ldmatrix.sync.aligned.m8n8.x4.shared.b16 {%0,%1,%2,%3}, [%4];"
        : "=r"(r0), "=r"(r1), "=r"(r2), "=r"(r3) : "r"(a));
}

__device__ __forceinline__ void ldsm4t(uint32_t& r0, uint32_t& r1,
                                       uint32_t& r2, uint32_t& r3, uint32_t a) {
    asm volatile("ldmatrix.sync.aligned.m8n8.x4.trans.shared.b16 {%0,%1,%2,%3}, [%4];"
        : "=r"(r0), "=r"(r1), "=r"(r2), "=r"(r3) : "r"(a));
}

__device__ __forceinline__ void cpa16(uint32_t dst, const void* src, int srcsize) {
    asm volatile("cp.async.cg.shared.global [%0], [%1], 16, %2;"
        :: "r"(dst), "l"(src), "r"(srcsize));
}
__device__ __forceinline__ void cpa_commit() {
    asm volatile("cp.async.commit_group;" ::: "memory");
}
template<int N>
__device__ __forceinline__ void cpa_wait() {
    asm volatile("cp.async.wait_group %0;" :: "n"(N) : "memory");
}

__device__ __forceinline__ float ex2(float x) {
    float y;
    asm("ex2.approx.ftz.f32 %0, %1;" : "=f"(y) : "f"(x));
    return y;
}

__device__ __forceinline__ uint32_t pk2h(float x, float y) {
    __half2 t = __floats2half2_rn(x, y);
    return *reinterpret_cast<uint32_t*>(&t);
}

__device__ __forceinline__ void fsplit_h(float v, __half& hi, __half& lo) {
    hi = __float2half_rn(v);
    lo = __float2half_rn(v - __half2float(hi));
}

__device__ __forceinline__ void stcs2(float* p, float a, float b) {
    asm volatile("st.global.cs.v2.f32 [%0], {%1,%2};" :: "l"(p), "f"(a), "f"(b));
}

// ---------------------------------------------------------------------------
// Weight conversion fp32 -> fp16 (+ QKV packing)
// ---------------------------------------------------------------------------
__global__ void convert_w(const float* __restrict__ qw, const float* __restrict__ kw,
                          const float* __restrict__ vw, const float* __restrict__ ow,
                          const float* __restrict__ f1w, const float* __restrict__ f2w,
                          const float* __restrict__ o1w,
                          const float* __restrict__ qb, const float* __restrict__ kb,
                          const float* __restrict__ vb) {
    int i = blockIdx.x * 256 + threadIdx.x;
    const int n1 = NLd*Dd*128;
    const int n3 = NLd*Dd*FCd;
    const int n5 = Dd*Dd;
    if (i < n1) {
        int l = i / (Dd*128), rem = i % (Dd*128);
        size_t b = (size_t)(l*3)*Dd*128 + rem;
        g_qkvw[b]            = __float2half_rn(qw[i]);
        g_qkvw[b + Dd*128]   = __float2half_rn(kw[i]);
        g_qkvw[b + 2*Dd*128] = __float2half_rn(vw[i]);
        g_ow[i]              = __float2half_rn(ow[i]);
    }
    if (i < n3) {
        g_f1w[i] = __float2half_rn(f1w[i]);
        g_f2w[i] = __float2half_rn(f2w[i]);
    }
    if (i < n5) g_o1w[i] = __float2half_rn(o1w[i]);
    if (i < NLd*128) {
        int l = i >> 7, n = i & 127;
        g_qkvb[(l*3+0)*128 + n] = qb[i];
        g_qkvb[(l*3+1)*128 + n] = kb[i];
        g_qkvb[(l*3+2)*128 + n] = vb[i];
    }
}

// ---------------------------------------------------------------------------
// Embed: h = x @ in_w + in_b (split fp16)
// ---------------------------------------------------------------------------
__global__ void embed_kernel(const float* __restrict__ x,
                             const float* __restrict__ in_w,
                             const float* __restrict__ in_b) {
    int t = blockIdx.x, d = threadIdx.x;
    float x0 = x[t*2], x1 = x[t*2+1];
    float v = fmaf(x0, in_w[d], fmaf(x1, in_w[Dd + d], in_b[d]));
    size_t ix = (size_t)t*Dd + d;
    fsplit_h(v, g_hh[ix], g_hl[ix]);
}

// ---------------------------------------------------------------------------
// GEMM core: tile 128x64, 512 threads. 2-term split fp16 MMA
// (A = hi+lo fp16, W = single fp16). OM: 0=fp32, 1=split fp16, 2=fp16*scale.
// ---------------------------------------------------------------------------
template<int K, int OM, bool RELU>
__device__ __forceinline__ void gemm_body(
        const __half* __restrict__ Ahi,
        const __half* __restrict__ Alo,
        const __half* __restrict__ W,
        const float* __restrict__ bias,
        float* __restrict__ outF,
        __half* __restrict__ outH1,
        __half* __restrict__ outH2, float oscale,
        int N, int row0, int col0) {
    extern __shared__ __half smh[];
    constexpr int SA = K + 8;
    __half* sAh = smh;
    __half* sAl = smh + 128 * SA;
    __half* sW  = smh + 256 * SA;

    const int tid = threadIdx.x, lane = tid & 31, warp = tid >> 5;

    constexpr int AV = K / 8;
    #pragma unroll 2
    for (int i = tid; i < 128 * AV; i += 512) {
        int r = i / AV, c = (i % AV) * 8;
        size_t g = (size_t)(row0 + r)*K + c;
        *reinterpret_cast<uint4*>(&sAh[r*SA + c]) = *reinterpret_cast<const uint4*>(&Ahi[g]);
        *reinterpret_cast<uint4*>(&sAl[r*SA + c]) = *reinterpret_cast<const uint4*>(&Alo[g]);
    }
    #pragma unroll 2
    for (int i = tid; i < 64 * K / 4; i += 512) {
        int k = i >> 4, n4 = (i & 15) * 4;
        size_t g = (size_t)k*N + col0 + n4;
        uint2 w2 = *reinterpret_cast<const uint2*>(&W[g]);
        __half tw[4]; *reinterpret_cast<uint2*>(tw) = w2;
        #pragma unroll
        for (int j = 0; j < 4; j++) sW[(n4+j)*SA + k] = tw[j];
    }
    __syncthreads();

    float acc[4][4];
    #pragma unroll
    for (int i = 0; i < 4; i++)
        #pragma unroll
        for (int j = 0; j < 4; j++) acc[i][j] = 0.f;

    const int mwarp = warp >> 1, nwarp = warp & 1;
    const int ar = mwarp*16 + (lane >> 2);
    const int ac = (lane & 3) * 2;
    #pragma unroll
    for (int kk = 0; kk < K/16; kk++) {
        uint32_t ah[4], al[4];
        {
            const __half* pa = &sAh[ar*SA + kk*16 + ac];
            ah[0] = *(const uint32_t*)pa;
            ah[1] = *(const uint32_t*)(pa + 8*SA);
            ah[2] = *(const uint32_t*)(pa + 8);
            ah[3] = *(const uint32_t*)(pa + 8*SA + 8);
            const __half* pl = &sAl[ar*SA + kk*16 + ac];
            al[0] = *(const uint32_t*)pl;
            al[1] = *(const uint32_t*)(pl + 8*SA);
            al[2] = *(const uint32_t*)(pl + 8);
            al[3] = *(const uint32_t*)(pl + 8*SA + 8);
        }
        #pragma unroll
        for (int nt = 0; nt < 4; nt++) {
            int nrow = nwarp*32 + nt*8 + (lane>>2);
            const __half* pb = &sW[nrow*SA + kk*16 + ac];
            uint32_t b0 = *(const uint32_t*)pb;
            uint32_t b1 = *(const uint32_t*)(pb + 8);
            mma16816h(acc[nt], ah, b0, b1);
            mma16816h(acc[nt], al, b0, b1);
        }
    }

    const int orow = row0 + mwarp*16 + (lane >> 2);
    #pragma unroll
    for (int nt = 0; nt < 4; nt++) {
        int c = col0 + nwarp*32 + nt*8 + (lane & 3)*2;
        float b0v = bias[c], b1v = bias[c+1];
        #pragma unroll
        for (int half = 0; half < 2; half++) {
            int r = orow + half*8;
            float v0 = acc[nt][half*2+0] + b0v;
            float v1 = acc[nt][half*2+1] + b1v;
            if (RELU) { v0 = fmaxf(v0, 0.f); v1 = fmaxf(v1, 0.f); }
            size_t o = (size_t)r*N + c;
            if (OM == 0) { outF[o] = v0; outF[o+1] = v1; }
            if (OM == 1) {
                __half h0, l0, h1, l1;
                fsplit_h(v0, h0, l0);
                fsplit_h(v1, h1, l1);
                outH1[o] = h0; outH1[o+1] = h1;
                outH2[o] = l0; outH2[o+1] = l1;
            }
            if (OM == 2) {
                __half2 t = __floats2half2_rn(v0*oscale, v1*oscale);
                *reinterpret_cast<__half2*>(&outH1[o]) = t;
            }
        }
    }
}

template<int K, int OM, bool RELU>
__global__ __launch_bounds__(512) void gemm_bias(
        const __half* __restrict__ Ahi, const __half* __restrict__ Alo,
        const __half* __restrict__ W,
        const float* __restrict__ bias,
        float* __restrict__ outF,
        __half* __restrict__ outH1, __half* __restrict__ outH2,
        int N) {
    gemm_body<K, OM, RELU>(Ahi, Alo, W, bias, outF, outH1, outH2, 1.f,
                           N, blockIdx.x*128, blockIdx.y*64);
}

// Fused QKV: grid (126, 6); writes fp16 (Q pre-scaled by SCALE*log2e)
__global__ __launch_bounds__(512) void gemm_qkv(int layer) {
    int sel = blockIdx.y >> 1;
    int col0 = (blockIdx.y & 1) * 64;
    const __half* W = g_qkvw + ((size_t)(layer*3 + sel))*Dd*128;
    const float* bias = g_qkvb + (layer*3 + sel)*128;
    __half* oh = g_qkv + (size_t)sel*BLd*128;
    float oscale = (sel == 0) ? SC2f : 1.f;
    gemm_body<256, 2, false>(g_hh, g_hl, W, bias, nullptr, oh, nullptr, oscale,
                             128, blockIdx.x*128, col0);
}

// ---------------------------------------------------------------------------
// GEMM (tile 128 x 256, full rows) + fused residual + LayerNorm.
// Residual read from split fp16 (hh+hl); writes split fp16 only.
// ---------------------------------------------------------------------------
#define LNSS 260

template<int K>
__global__ __launch_bounds__(512) void gemm_ln(
        const __half* __restrict__ Ahi,
        const __half* __restrict__ Alo,
        const __half* __restrict__ W,
        const float* __restrict__ bias,
        const float* __restrict__ gam,
        const float* __restrict__ bet) {
    extern __shared__ __half smh[];
    constexpr int SA = K + 8;
    __half* sAh = smh;
    __half* sAl = smh + 128 * SA;
    __half* sW  = smh + 256 * SA;
    float* sv = (float*)smh;

    const int tid = threadIdx.x, lane = tid & 31, warp = tid >> 5;
    const int row0 = blockIdx.x * 128;

    constexpr int AV = K / 8;
    #pragma unroll 2
    for (int i = tid; i < 128 * AV; i += 512) {
        int r = i / AV, c = (i % AV) * 8;
        size_t g = (size_t)(row0 + r)*K + c;
        *reinterpret_cast<uint4*>(&sAh[r*SA + c]) = *reinterpret_cast<const uint4*>(&Ahi[g]);
        *reinterpret_cast<uint4*>(&sAl[r*SA + c]) = *reinterpret_cast<const uint4*>(&Alo[g]);
    }
    #pragma unroll 2
    for (int i = tid; i < 256 * K / 4; i += 512) {
        int k = i / 64, n4 = (i % 64) * 4;
        size_t g = (size_t)k*Dd + n4;
        uint2 w2 = *reinterpret_cast<const uint2*>(&W[g]);
        __half tw[4]; *reinterpret_cast<uint2*>(tw) = w2;
        #pragma unroll
        for (int j = 0; j < 4; j++) sW[(n4+j)*SA + k] = tw[j];
    }
    __syncthreads();

    float acc[16][4];
    #pragma unroll
    for (int i = 0; i < 16; i++)
        #pragma unroll
        for (int j = 0; j < 4; j++) acc[i][j] = 0.f;

    const int mwarp = warp >> 1, nwarp = warp & 1;
    const int ar = mwarp*16 + (lane >> 2);
    const int ac = (lane & 3) * 2;
    #pragma unroll
    for (int kk = 0; kk < K/16; kk++) {
        uint32_t ah[4], al[4];
        {
            const __half* pa = &sAh[ar*SA + kk*16 + ac];
            ah[0] = *(const uint32_t*)pa;
            ah[1] = *(const uint32_t*)(pa + 8*SA);
            ah[2] = *(const uint32_t*)(pa + 8);
            ah[3] = *(const uint32_t*)(pa + 8*SA + 8);
            const __half* pl = &sAl[ar*SA + kk*16 + ac];
            al[0] = *(const uint32_t*)pl;
            al[1] = *(const uint32_t*)(pl + 8*SA);
            al[2] = *(const uint32_t*)(pl + 8);
            al[3] = *(const uint32_t*)(pl + 8*SA + 8);
        }
        #pragma unroll
        for (int nt = 0; nt < 16; nt++) {
            int nrow = nwarp*128 + nt*8 + (lane>>2);
            const __half* pb = &sW[nrow*SA + kk*16 + ac];
            uint32_t b0 = *(const uint32_t*)pb;
            uint32_t b1 = *(const uint32_t*)(pb + 8);
            mma16816h(acc[nt], ah, b0, b1);
            mma16816h(acc[nt], al, b0, b1);
        }
    }
    __syncthreads();

    {
        const int r0 = mwarp*16 + (lane >> 2);
        #pragma unroll
        for (int nt = 0; nt < 16; nt++) {
            int c = nwarp*128 + nt*8 + (lane & 3)*2;
            float b0v = bias[c], b1v = bias[c+1];
            sv[ r0     *LNSS + c]     = acc[nt][0] + b0v;
            sv[ r0     *LNSS + c + 1] = acc[nt][1] + b1v;
            sv[(r0 + 8)*LNSS + c]     = acc[nt][2] + b0v;
            sv[(r0 + 8)*LNSS + c + 1] = acc[nt][3] + b1v;
        }
    }
    __syncthreads();

    #pragma unroll 1
    for (int rr = 0; rr < 8; rr++) {
        int row = warp*8 + rr;
        int token = row0 + row;
        const __half* hph = &g_hh[(size_t)token*Dd];
        const __half* hpl = &g_hl[(size_t)token*Dd];
        float x[8], s = 0.f;
        #pragma unroll
        for (int j = 0; j < 8; j++) {
            int cix = lane*8 + j;
            x[j] = __half2float(hph[cix]) + __half2float(hpl[cix])
                 + sv[row*LNSS + cix];
            s += x[j];
        }
        #pragma unroll
        for (int o = 16; o; o >>= 1) s += __shfl_xor_sync(~0u, s, o);
        float mean = s * (1.f/256.f);
        float v = 0.f;
        #pragma unroll
        for (int j = 0; j < 8; j++) { float d = x[j] - mean; v += d*d; }
        #pragma unroll
        for (int o = 16; o; o >>= 1) v += __shfl_xor_sync(~0u, v, o);
        float rstd = rsqrtf(v * (1.f/256.f) + EPSLN);
        #pragma unroll
        for (int j = 0; j < 8; j++) {
            int cix = lane*8 + j;
            float y = (x[j] - mean)*rstd*gam[cix] + bet[cix];
            size_t ix = (size_t)token*Dd + cix;
            fsplit_h(y, g_hh[ix], g_hl[ix]);
        }
    }
}

// ---------------------------------------------------------------------------
// Attention v9 (fp16): 256-query tile, 256 threads (8 warps x 32 rows ->
// every K/V ldmatrix feeds 2 MMA row-blocks; staging amortized over 2x
// queries). Single-term fp16 MMA, Q pre-scaled by SCALE*log2e.
// Pass A: row sums (4-buffer K ring, 2 chunks/barrier). Pass B: QK, P (.cs),
// PV. smem 40KB, <=128 regs -> 2 CTAs/SM; grid 256 -> single wave.
// Zfilled padding keys -> score exactly 0 -> exp exactly 1 -> subtract 32.
// ---------------------------------------------------------------------------
#define QT 256
#define KT 128
#define NCH 16
#define NPAD 32.0f

#define BUFB 10240                 // bytes per 128x40-half buffer
#define SM_ATTN_BYTES (4*BUFB)     // 40960

__device__ __forceinline__ void stage1(uint32_t sm_u, int bufoff, int ch,
        const __half* P, size_t base, int tid) {
    const int k0 = ch * KT;
    #pragma unroll
    for (int it = 0; it < 2; it++) {
        int o = tid + it*256;
        int r = o >> 2;
        int c = (o & 3) * 8;
        int s = k0 + r;
        bool ok = s < Ld;
        const __half* src = P + base + (size_t)(ok ? s : 0)*128 + c;
        uint32_t dst = sm_u + bufoff + (r*40 + c)*2;
        cpa16(dst, src, ok ? 16 : 0);
    }
}

// Pass A stats: both 16-row blocks share each K fragment.
__device__ __forceinline__ void qk_stats_chunk(
        uint32_t kh_u, int laneK,
        const uint32_t aq[2][2][4],
        float s[4]) {
    #pragma unroll 1
    for (int gq = 0; gq < 4; gq++) {
        float acc[2][4][4];
        #pragma unroll
        for (int rb = 0; rb < 2; rb++)
            #pragma unroll
            for (int i = 0; i < 4; i++)
                #pragma unroll
                for (int j = 0; j < 4; j++) acc[rb][i][j] = 0.f;
        #pragma unroll
        for (int pair = 0; pair < 2; pair++) {
            int be = (gq*32 + pair*16)*40;
            #pragma unroll
            for (int kk = 0; kk < 2; kk++) {
                uint32_t b0, b1, b2, b3;
                uint32_t off = (be + kk*16 + laneK)*2;
                ldsm4(b0, b1, b2, b3, kh_u + off);
                mma16816h(acc[0][pair*2  ], aq[0][kk], b0, b1);
                mma16816h(acc[0][pair*2+1], aq[0][kk], b2, b3);
                mma16816h(acc[1][pair*2  ], aq[1][kk], b0, b1);
                mma16816h(acc[1][pair*2+1], aq[1][kk], b2, b3);
            }
        }
        #pragma unroll
        for (int rb = 0; rb < 2; rb++)
            #pragma unroll
            for (int nt = 0; nt < 4; nt++) {
                s[rb*2+0] += ex2(acc[rb][nt][0]) + ex2(acc[rb][nt][1]);
                s[rb*2+1] += ex2(acc[rb][nt][2]) + ex2(acc[rb][nt][3]);
            }
    }
}

// Pass B chunk: QK + exp + P store + PV, 2 row-blocks share every fragment.
template<bool MASK>
__device__ __forceinline__ void qk_emit_chunk(
        uint32_t kh_u, uint32_t vh_u, int laneK, int laneV,
        const uint32_t aq[2][2][4],
        int k0, int fc, const float inv[4],
        float* const prow[4], const bool wr[4],
        float oacc[2][4][4]) {
    #pragma unroll 1
    for (int g = 0; g < 8; g++) {
        int kbe = g*16*40;
        float acc[2][2][4];
        #pragma unroll
        for (int rb = 0; rb < 2; rb++)
            #pragma unroll
            for (int i = 0; i < 2; i++)
                #pragma unroll
                for (int j = 0; j < 4; j++) acc[rb][i][j] = 0.f;
        #pragma unroll
        for (int kk = 0; kk < 2; kk++) {
            uint32_t b0, b1, b2, b3;
            uint32_t off = (kbe + kk*16 + laneK)*2;
            ldsm4(b0, b1, b2, b3, kh_u + off);
            mma16816h(acc[0][0], aq[0][kk], b0, b1);
            mma16816h(acc[0][1], aq[0][kk], b2, b3);
            mma16816h(acc[1][0], aq[1][kk], b0, b1);
            mma16816h(acc[1][1], aq[1][kk], b2, b3);
        }
        int colb = k0 + g*16 + fc;
        bool ok0 = !MASK || (colb < Ld);
        bool ok1 = !MASK || (colb + 8 < Ld);

        uint32_t ah[2][4];
        #pragma unroll
        for (int rb = 0; rb < 2; rb++) {
            float i0 = inv[rb*2], i1 = inv[rb*2+1];
            float p00 = ok0 ? ex2(acc[rb][0][0])*i0 : 0.f;
            float p01 = ok0 ? ex2(acc[rb][0][1])*i0 : 0.f;
            float p02 = ok0 ? ex2(acc[rb][0][2])*i1 : 0.f;
            float p03 = ok0 ? ex2(acc[rb][0][3])*i1 : 0.f;
            float p10 = ok1 ? ex2(acc[rb][1][0])*i0 : 0.f;
            float p11 = ok1 ? ex2(acc[rb][1][1])*i0 : 0.f;
            float p12 = ok1 ? ex2(acc[rb][1][2])*i1 : 0.f;
            float p13 = ok1 ? ex2(acc[rb][1][3])*i1 : 0.f;

            if (wr[rb*2]) {
                if (ok0) stcs2(&prow[rb*2][colb],     p00, p01);
                if (ok1) stcs2(&prow[rb*2][colb + 8], p10, p11);
            }
            if (wr[rb*2+1]) {
                if (ok0) stcs2(&prow[rb*2+1][colb],     p02, p03);
                if (ok1) stcs2(&prow[rb*2+1][colb + 8], p12, p13);
            }
            ah[rb][0] = pk2h(p00, p01);
            ah[rb][1] = pk2h(p02, p03);
            ah[rb][2] = pk2h(p10, p11);
            ah[rb][3] = pk2h(p12, p13);
        }

        #pragma unroll
        for (int dp = 0; dp < 2; dp++) {
            uint32_t v0, v1, v2, v3;
            uint32_t off = (kbe + dp*16 + laneV)*2;
            ldsm4t(v0, v1, v2, v3, vh_u + off);
            mma16816h(oacc[0][dp*2  ], ah[0], v0, v1);
            mma16816h(oacc[0][dp*2+1], ah[0], v2, v3);
            mma16816h(oacc[1][dp*2  ], ah[1], v0, v1);
            mma16816h(oacc[1][dp*2+1], ah[1], v2, v3);
        }
    }
}

__global__ __launch_bounds__(256, 2) void attn_kernel(
        const __half* __restrict__ qkv,
        float* __restrict__ Pout,
        __half* __restrict__ Oh, __half* __restrict__ Ol) {
    extern __shared__ __half smh[];
    uint32_t sm_u = (uint32_t)__cvta_generic_to_shared(smh);

    const int tid = threadIdx.x, lane = tid & 31, warp = tid >> 5;
    const int bh = blockIdx.y;
    const int b  = bh >> 2, h = bh & 3;
    const int q0 = blockIdx.x * QT;
    const size_t base = ((size_t)b*Ld*Hd + h)*DKd;
    const __half* Q = qkv;
    const __half* K = qkv + (size_t)BLd*128;
    const __half* V = qkv + (size_t)2*BLd*128;

    const int mrow = warp * 32;
    const int fr = lane >> 2, fc = (lane & 3) * 2;
    const int lr = lane & 7, sel = lane >> 3;
    const int laneK = ((sel>>1)*8 + lr)*40 + (sel&1)*8;
    const int laneV = ((sel&1)*8 + lr)*40 + (sel>>1)*8;

    const int rg[4] = { q0 + mrow + fr, q0 + mrow + fr + 8,
                        q0 + mrow + fr + 16, q0 + mrow + fr + 24 };
    bool wr[4];
    #pragma unroll
    for (int i = 0; i < 4; i++) wr[i] = (rg[i] < Ld);

    uint32_t aq[2][2][4];
    #pragma unroll
    for (int rb = 0; rb < 2; rb++) {
        #pragma unroll
        for (int kk = 0; kk < 2; kk++) {
            int c = kk*16 + fc;
            size_t g0 = base + (size_t)rg[rb*2]*128 + c;
            size_t g1 = base + (size_t)rg[rb*2+1]*128 + c;
            aq[rb][kk][0] = wr[rb*2]   ? *(const uint32_t*)&Q[g0]     : 0;
            aq[rb][kk][1] = wr[rb*2+1] ? *(const uint32_t*)&Q[g1]     : 0;
            aq[rb][kk][2] = wr[rb*2]   ? *(const uint32_t*)&Q[g0 + 8] : 0;
            aq[rb][kk][3] = wr[rb*2+1] ? *(const uint32_t*)&Q[g1 + 8] : 0;
        }
    }

    float s[4] = {0.f, 0.f, 0.f, 0.f};

    // ======== PASS A: row sums (K only, 4-buffer ring, 2 chunks/sync) ====
    stage1(sm_u, 0*BUFB, 0, K, base, tid);
    stage1(sm_u, 1*BUFB, 1, K, base, tid); cpa_commit();
    stage1(sm_u, 2*BUFB, 2, K, base, tid);
    stage1(sm_u, 3*BUFB, 3, K, base, tid); cpa_commit();
    #pragma unroll 1
    for (int it = 0; it < 8; it++) {
        if (it < 7) cpa_wait<1>(); else cpa_wait<0>();
        __syncthreads();
        int b0 = (it & 1) ? 2 : 0;
        qk_stats_chunk(sm_u + b0*BUFB,     laneK, aq, s);
        qk_stats_chunk(sm_u + (b0+1)*BUFB, laneK, aq, s);
        __syncthreads();
        if (it < 6) {
            stage1(sm_u, b0*BUFB,     2*it+4, K, base, tid);
            stage1(sm_u, (b0+1)*BUFB, 2*it+5, K, base, tid);
            cpa_commit();
        }
    }

    // prologue for pass B overlaps the reduction: K in bufs 0/1, V in 2/3
    stage1(sm_u, 0*BUFB, 0, K, base, tid);
    stage1(sm_u, 2*BUFB, 0, V, base, tid); cpa_commit();
    stage1(sm_u, 1*BUFB, 1, K, base, tid);
    stage1(sm_u, 3*BUFB, 1, V, base, tid); cpa_commit();

    float inv[4];
    #pragma unroll
    for (int i = 0; i < 4; i++) {
        float v = s[i];
        v += __shfl_xor_sync(~0u, v, 1);
        v += __shfl_xor_sync(~0u, v, 2);
        inv[i] = 1.f / (v - NPAD);
    }

    // ======== PASS B: P out + PV ========
    float oacc[2][4][4];
    #pragma unroll
    for (int rb = 0; rb < 2; rb++)
        #pragma unroll
        for (int i = 0; i < 4; i++)
            #pragma unroll
            for (int j = 0; j < 4; j++) oacc[rb][i][j] = 0.f;

    float* prow[4];
    #pragma unroll
    for (int i = 0; i < 4; i++)
        prow[i] = &Pout[((size_t)bh*Ld + rg[i])*Ld];

    #pragma unroll 1
    for (int ch = 0; ch < NCH; ch++) {
        if (ch < NCH-1) cpa_wait<1>(); else cpa_wait<0>();
        __syncthreads();
        int buf = ch & 1;
        uint32_t kh_u = sm_u + buf*BUFB;
        uint32_t vh_u = sm_u + (2 + buf)*BUFB;
        if (ch < NCH-1)
            qk_emit_chunk<false>(kh_u, vh_u, laneK, laneV, aq,
                                 ch*KT, fc, inv, prow, wr, oacc);
        else
            qk_emit_chunk<true >(kh_u, vh_u, laneK, laneV, aq,
                                 ch*KT, fc, inv, prow, wr, oacc);
        __syncthreads();
        if (ch + 2 < NCH) {
            stage1(sm_u, buf*BUFB,       ch+2, K, base, tid);
            stage1(sm_u, (2 + buf)*BUFB, ch+2, V, base, tid);
            cpa_commit();
        }
    }

    // ---- write O (split fp16) ----
    #pragma unroll
    for (int rb = 0; rb < 2; rb++) {
        #pragma unroll
        for (int dt = 0; dt < 4; dt++) {
            int d = dt*8 + fc;
            if (wr[rb*2]) {
                size_t g = base + (size_t)rg[rb*2]*128 + d;
                __half hh, ll;
                fsplit_h(oacc[rb][dt][0], hh, ll); Oh[g]   = hh; Ol[g]   = ll;
                fsplit_h(oacc[rb][dt][1], hh, ll); Oh[g+1] = hh; Ol[g+1] = ll;
            }
            if (wr[rb*2+1]) {
                size_t g = base + (size_t)rg[rb*2+1]*128 + d;
                __half hh, ll;
                fsplit_h(oacc[rb][dt][2], hh, ll); Oh[g]   = hh; Ol[g]   = ll;
                fsplit_h(oacc[rb][dt][3], hh, ll); Oh[g+1] = hh; Ol[g+1] = ll;
            }
        }
    }
}

// ---------------------------------------------------------------------------
// Final head tail: out = relu_h(g_tmp fp32) @ o2w + o2b   (warp per token)
// ---------------------------------------------------------------------------
__global__ __launch_bounds__(256) void head2_kernel(const float* __restrict__ o2w,
                                                    const float* __restrict__ o2b,
                                                    float* __restrict__ out) {
    int warp = threadIdx.x >> 5, lane = threadIdx.x & 31;
    int token = blockIdx.x * 8 + warp;
    const float* hp = &g_tmp[(size_t)token*Dd];
    float a0 = 0.f, a1 = 0.f;
    #pragma unroll
    for (int j = 0; j < 8; j++) {
        int k = lane + j*32;
        float hv = hp[k];
        a0 = fmaf(hv, o2w[k*2],   a0);
        a1 = fmaf(hv, o2w[k*2+1], a1);
    }
    #pragma unroll
    for (int o = 16; o; o >>= 1) {
        a0 += __shfl_xor_sync(~0u, a0, o);
        a1 += __shfl_xor_sync(~0u, a1, o);
    }
    if (lane == 0) {
        out[(size_t)token*2]     = a0 + o2b[0];
        out[(size_t)token*2 + 1] = a1 + o2b[1];
    }
}

// ---------------------------------------------------------------------------
// Host orchestration
// ---------------------------------------------------------------------------
static inline void* symaddr(const void* s) {
    void* p = nullptr;
    cudaGetSymbolAddress(&p, s);
    return p;
}

extern "C" void kernel_launch(void* const* d_in, const int* in_sizes, int n_in,
                              void* d_out, int out_size) {
    const float* x    = (const float*)d_in[0];
    const float* in_w = (const float*)d_in[1];
    const float* in_b = (const float*)d_in[2];
    const float* qw   = (const float*)d_in[3];
    const float* qb   = (const float*)d_in[4];
    const float* kw   = (const float*)d_in[5];
    const float* kb   = (const float*)d_in[6];
    const float* vw   = (const float*)d_in[7];
    const float* vb   = (const float*)d_in[8];
    const float* ow   = (const float*)d_in[9];
    const float* ob   = (const float*)d_in[10];
    const float* f1w  = (const float*)d_in[11];
    const float* f1b  = (const float*)d_in[12];
    const float* f2w  = (const float*)d_in[13];
    const float* f2b  = (const float*)d_in[14];
    const float* n1g  = (const float*)d_in[15];
    const float* n1b  = (const float*)d_in[16];
    const float* n2g  = (const float*)d_in[17];
    const float* n2b  = (const float*)d_in[18];
    const float* o1w  = (const float*)d_in[19];
    const float* o1b  = (const float*)d_in[20];
    const float* o2w  = (const float*)d_in[21];
    const float* o2b  = (const float*)d_in[22];

    float* outp     = (float*)d_out;
    float* attn_out = outp + (size_t)Bd*Ld*2;

    __half* p_hh   = (__half*)symaddr(g_hh);
    __half* p_hl   = (__half*)symaddr(g_hl);
    __half* p_qkv  = (__half*)symaddr(g_qkv);
    __half* p_oh   = (__half*)symaddr(g_oh);
    __half* p_ol   = (__half*)symaddr(g_ol);
    __half* p_fh   = (__half*)symaddr(g_fh);
    __half* p_fl   = (__half*)symaddr(g_fl);
    float*  p_tmp  = (float*)symaddr(g_tmp);
    __half* p_ow   = (__half*)symaddr(g_ow);
    __half* p_f1w  = (__half*)symaddr(g_f1w);
    __half* p_f2w  = (__half*)symaddr(g_f2w);
    __half* p_o1w  = (__half*)symaddr(g_o1w);

    const int SM_G256  = (2*128*(256+8) + 64*(256+8))*2;      // 168960
    const int SM_LN128 = (2*128*(128+8) + 256*(128+8))*2;     // 139264
    const int SM_LN64_OP = (2*128*(64+8) + 256*(64+8))*2;     // 73728
    const int SM_LNSLAB  = 128*LNSS*4;                        // 133120
    const int SM_LN64  = SM_LN64_OP > SM_LNSLAB ? SM_LN64_OP : SM_LNSLAB;
    const int SM_LN128F = SM_LN128 > SM_LNSLAB ? SM_LN128 : SM_LNSLAB;

    cudaFuncSetAttribute(gemm_qkv, cudaFuncAttributeMaxDynamicSharedMemorySize, SM_G256);
    cudaFuncSetAttribute(gemm_bias<256,1,true >, cudaFuncAttributeMaxDynamicSharedMemorySize, SM_G256);
    cudaFuncSetAttribute(gemm_bias<256,0,true >, cudaFuncAttributeMaxDynamicSharedMemorySize, SM_G256);
    cudaFuncSetAttribute(gemm_ln<128>, cudaFuncAttributeMaxDynamicSharedMemorySize, SM_LN128F);
    cudaFuncSetAttribute(gemm_ln<64 >, cudaFuncAttributeMaxDynamicSharedMemorySize, SM_LN64);
    cudaFuncSetAttribute(attn_kernel, cudaFuncAttributeMaxDynamicSharedMemorySize, SM_ATTN_BYTES);

    convert_w<<<384, 256>>>(qw, kw, vw, ow, f1w, f2w, o1w, qb, kb, vb);
    embed_kernel<<<BLd, Dd>>>(x, in_w, in_b);

    const dim3 gQKV (BLd/128, 6);
    const dim3 gProj(BLd/128, 4);   // N=256 (head only)
    const dim3 gF1  (BLd/128, 1);   // N=64
    const dim3 gLN  (BLd/128);
    const dim3 gAttn((Ld + QT - 1)/QT, Bd*Hd);

    for (int i = 0; i < NLd; i++) {
        gemm_qkv<<<gQKV, 512, SM_G256>>>(i);

        attn_kernel<<<gAttn, 256, SM_ATTN_BYTES>>>(
            p_qkv, attn_out + (size_t)i*Bd*Hd*Ld*Ld, p_oh, p_ol);

        // o-projection + residual + LN1 (fused)
        gemm_ln<128><<<gLN, 512, SM_LN128F>>>(
            p_oh, p_ol, p_ow + (size_t)i*128*Dd,
            ob + i*Dd, n1g + i*Dd, n1b + i*Dd);

        // FFN1 (relu, split fp16 out)
        gemm_bias<256,1,true><<<gF1, 512, SM_G256>>>(
            p_hh, p_hl, p_f1w + (size_t)i*Dd*FCd,
            f1b + i*FCd, nullptr, p_fh, p_fl, FCd);

        // FFN2 + residual + LN2 (fused)
        gemm_ln<64><<<gLN, 512, SM_LN64>>>(
            p_fh, p_fl, p_f2w + (size_t)i*FCd*Dd,
            f2b + i*Dd, n2g + i*Dd, n2b + i*Dd);
    }

    gemm_bias<256,0,true><<<gProj, 512, SM_G256>>>(
        p_hh, p_hl, p_o1w, o1b, p_tmp, nullptr, nullptr, Dd);
    head2_kernel<<<BLd/8, 256>>>(o2w, o2b, outp);
}

// round 15
// speedup vs baseline: 1.4420x; 1.4420x over previous
#include <cuda_runtime.h>
#include <cuda_bf16.h>
#include <cuda_fp16.h>
#include <stdint.h>

#define Bd  8
#define Ld  2016
#define Hd  4
#define DKd 32
#define Dd  256
#define FCd 64
#define NLd 3
#define BLd (Bd*Ld)          // 16128 tokens

#define SC2f 0.09016844005556f   // (1/sqrt(256)) * log2(e)
#define EPSLN 1e-5f

// ---------------------------------------------------------------------------
// Device scratch. Residual stream: split fp16 only. Weights: fp16.
// ---------------------------------------------------------------------------
__device__ __align__(128) __half  g_hh   [BLd*Dd];
__device__ __align__(128) __half  g_hl   [BLd*Dd];
__device__ __align__(128) __half  g_qkv  [3*BLd*128];   // fp16 (Q pre-scaled)
__device__ __align__(128) __half  g_oh   [BLd*128];
__device__ __align__(128) __half  g_ol   [BLd*128];
__device__ __align__(128) float   g_tmp  [BLd*Dd];
__device__ __align__(128) __half  g_fh   [BLd*FCd];
__device__ __align__(128) __half  g_fl   [BLd*FCd];
// fp16 weights
__device__ __align__(128) __half  g_qkvw [NLd*3*Dd*128];
__device__ __align__(128) float   g_qkvb [NLd*3*128];
__device__ __align__(128) __half  g_ow   [NLd*128*Dd];
__device__ __align__(128) __half  g_f1w  [NLd*Dd*FCd];
__device__ __align__(128) __half  g_f2w  [NLd*FCd*Dd];
__device__ __align__(128) __half  g_o1w  [Dd*Dd];

// ---------------------------------------------------------------------------
// helpers
// ---------------------------------------------------------------------------
__device__ __forceinline__ void mma16816h(float* d, const uint32_t* a,
                                          uint32_t b0, uint32_t b1) {
    asm volatile(
        "mma.sync.aligned.m16n8k16.row.col.f32.f16.f16.f32 "
        "{%0,%1,%2,%3}, {%4,%5,%6,%7}, {%8,%9}, {%0,%1,%2,%3};"
        : "+f"(d[0]), "+f"(d[1]), "+f"(d[2]), "+f"(d[3])
        : "r"(a[0]), "r"(a[1]), "r"(a[2]), "r"(a[3]), "r"(b0), "r"(b1));
}

__device__ __forceinline__ void ldsm4(uint32_t& r0, uint32_t& r1,
                                      uint32_t& r2, uint32_t& r3, uint32_t a) {
    asm volatile("ldmatrix.sync.aligned.m8n8.x4.shared.b16 {%0,%1,%2,%3}, [%4];"
        : "=r"(r0), "=r"(r1), "=r"(r2), "=r"(r3) : "r"(a));
}

__device__ __forceinline__ void ldsm4t(uint32_t& r0, uint32_t& r1,
                                       uint32_t& r2, uint32_t& r3, uint32_t a) {
    asm volatile("ldmatrix.sync.aligned.m8n8.x4.trans.shared.b16 {%0,%1,%2,%3}, [%4];"
        : "=r"(r0), "=r"(r1), "=r"(r2), "=r"(r3) : "r"(a));
}

__device__ __forceinline__ void cpa16(uint32_t dst, const void* src, int srcsize) {
    asm volatile("cp.async.cg.shared.global [%0], [%1], 16, %2;"
        :: "r"(dst), "l"(src), "r"(srcsize));
}
__device__ __forceinline__ void cpa_commit() {
    asm volatile("cp.async.commit_group;" ::: "memory");
}
template<int N>
__device__ __forceinline__ void cpa_wait() {
    asm volatile("cp.async.wait_group %0;" :: "n"(N) : "memory");
}

__device__ __forceinline__ float ex2(float x) {
    float y;
    asm("ex2.approx.ftz.f32 %0, %1;" : "=f"(y) : "f"(x));
    return y;
}

__device__ __forceinline__ uint32_t pk2h(float x, float y) {
    __half2 t = __floats2half2_rn(x, y);
    return *reinterpret_cast<uint32_t*>(&t);
}

__device__ __forceinline__ void fsplit_h(float v, __half& hi, __half& lo) {
    hi = __float2half_rn(v);
    lo = __float2half_rn(v - __half2float(hi));
}

__device__ __forceinline__ void stcs2(float* p, float a, float b) {
    asm volatile("st.global.cs.v2.f32 [%0], {%1,%2};" :: "l"(p), "f"(a), "f"(b));
}

// ---------------------------------------------------------------------------
// Weight conversion fp32 -> fp16 (+ QKV packing)
// ---------------------------------------------------------------------------
__global__ void convert_w(const float* __restrict__ qw, const float* __restrict__ kw,
                          const float* __restrict__ vw, const float* __restrict__ ow,
                          const float* __restrict__ f1w, const float* __restrict__ f2w,
                          const float* __restrict__ o1w,
                          const float* __restrict__ qb, const float* __restrict__ kb,
                          const float* __restrict__ vb) {
    int i = blockIdx.x * 256 + threadIdx.x;
    const int n1 = NLd*Dd*128;
    const int n3 = NLd*Dd*FCd;
    const int n5 = Dd*Dd;
    if (i < n1) {
        int l = i / (Dd*128), rem = i % (Dd*128);
        size_t b = (size_t)(l*3)*Dd*128 + rem;
        g_qkvw[b]            = __float2half_rn(qw[i]);
        g_qkvw[b + Dd*128]   = __float2half_rn(kw[i]);
        g_qkvw[b + 2*Dd*128] = __float2half_rn(vw[i]);
        g_ow[i]              = __float2half_rn(ow[i]);
    }
    if (i < n3) {
        g_f1w[i] = __float2half_rn(f1w[i]);
        g_f2w[i] = __float2half_rn(f2w[i]);
    }
    if (i < n5) g_o1w[i] = __float2half_rn(o1w[i]);
    if (i < NLd*128) {
        int l = i >> 7, n = i & 127;
        g_qkvb[(l*3+0)*128 + n] = qb[i];
        g_qkvb[(l*3+1)*128 + n] = kb[i];
        g_qkvb[(l*3+2)*128 + n] = vb[i];
    }
}

// ---------------------------------------------------------------------------
// Embed: h = x @ in_w + in_b (split fp16)
// ---------------------------------------------------------------------------
__global__ void embed_kernel(const float* __restrict__ x,
                             const float* __restrict__ in_w,
                             const float* __restrict__ in_b) {
    int t = blockIdx.x, d = threadIdx.x;
    float x0 = x[t*2], x1 = x[t*2+1];
    float v = fmaf(x0, in_w[d], fmaf(x1, in_w[Dd + d], in_b[d]));
    size_t ix = (size_t)t*Dd + d;
    fsplit_h(v, g_hh[ix], g_hl[ix]);
}

// ---------------------------------------------------------------------------
// GEMM core: tile 128x64, 512 threads. 2-term split fp16 MMA
// (A = hi+lo fp16, W = single fp16). OM: 0=fp32, 1=split fp16, 2=fp16*scale.
// ---------------------------------------------------------------------------
template<int K, int OM, bool RELU>
__device__ __forceinline__ void gemm_body(
        const __half* __restrict__ Ahi,
        const __half* __restrict__ Alo,
        const __half* __restrict__ W,
        const float* __restrict__ bias,
        float* __restrict__ outF,
        __half* __restrict__ outH1,
        __half* __restrict__ outH2, float oscale,
        int N, int row0, int col0) {
    extern __shared__ __half smh[];
    constexpr int SA = K + 8;
    __half* sAh = smh;
    __half* sAl = smh + 128 * SA;
    __half* sW  = smh + 256 * SA;

    const int tid = threadIdx.x, lane = tid & 31, warp = tid >> 5;

    constexpr int AV = K / 8;
    #pragma unroll 2
    for (int i = tid; i < 128 * AV; i += 512) {
        int r = i / AV, c = (i % AV) * 8;
        size_t g = (size_t)(row0 + r)*K + c;
        *reinterpret_cast<uint4*>(&sAh[r*SA + c]) = *reinterpret_cast<const uint4*>(&Ahi[g]);
        *reinterpret_cast<uint4*>(&sAl[r*SA + c]) = *reinterpret_cast<const uint4*>(&Alo[g]);
    }
    #pragma unroll 2
    for (int i = tid; i < 64 * K / 4; i += 512) {
        int k = i >> 4, n4 = (i & 15) * 4;
        size_t g = (size_t)k*N + col0 + n4;
        uint2 w2 = *reinterpret_cast<const uint2*>(&W[g]);
        __half tw[4]; *reinterpret_cast<uint2*>(tw) = w2;
        #pragma unroll
        for (int j = 0; j < 4; j++) sW[(n4+j)*SA + k] = tw[j];
    }
    __syncthreads();

    float acc[4][4];
    #pragma unroll
    for (int i = 0; i < 4; i++)
        #pragma unroll
        for (int j = 0; j < 4; j++) acc[i][j] = 0.f;

    const int mwarp = warp >> 1, nwarp = warp & 1;
    const int ar = mwarp*16 + (lane >> 2);
    const int ac = (lane & 3) * 2;
    #pragma unroll
    for (int kk = 0; kk < K/16; kk++) {
        uint32_t ah[4], al[4];
        {
            const __half* pa = &sAh[ar*SA + kk*16 + ac];
            ah[0] = *(const uint32_t*)pa;
            ah[1] = *(const uint32_t*)(pa + 8*SA);
            ah[2] = *(const uint32_t*)(pa + 8);
            ah[3] = *(const uint32_t*)(pa + 8*SA + 8);
            const __half* pl = &sAl[ar*SA + kk*16 + ac];
            al[0] = *(const uint32_t*)pl;
            al[1] = *(const uint32_t*)(pl + 8*SA);
            al[2] = *(const uint32_t*)(pl + 8);
            al[3] = *(const uint32_t*)(pl + 8*SA + 8);
        }
        #pragma unroll
        for (int nt = 0; nt < 4; nt++) {
            int nrow = nwarp*32 + nt*8 + (lane>>2);
            const __half* pb = &sW[nrow*SA + kk*16 + ac];
            uint32_t b0 = *(const uint32_t*)pb;
            uint32_t b1 = *(const uint32_t*)(pb + 8);
            mma16816h(acc[nt], ah, b0, b1);
            mma16816h(acc[nt], al, b0, b1);
        }
    }

    const int orow = row0 + mwarp*16 + (lane >> 2);
    #pragma unroll
    for (int nt = 0; nt < 4; nt++) {
        int c = col0 + nwarp*32 + nt*8 + (lane & 3)*2;
        float b0v = bias[c], b1v = bias[c+1];
        #pragma unroll
        for (int half = 0; half < 2; half++) {
            int r = orow + half*8;
            float v0 = acc[nt][half*2+0] + b0v;
            float v1 = acc[nt][half*2+1] + b1v;
            if (RELU) { v0 = fmaxf(v0, 0.f); v1 = fmaxf(v1, 0.f); }
            size_t o = (size_t)r*N + c;
            if (OM == 0) { outF[o] = v0; outF[o+1] = v1; }
            if (OM == 1) {
                __half h0, l0, h1, l1;
                fsplit_h(v0, h0, l0);
                fsplit_h(v1, h1, l1);
                outH1[o] = h0; outH1[o+1] = h1;
                outH2[o] = l0; outH2[o+1] = l1;
            }
            if (OM == 2) {
                __half2 t = __floats2half2_rn(v0*oscale, v1*oscale);
                *reinterpret_cast<__half2*>(&outH1[o]) = t;
            }
        }
    }
}

template<int K, int OM, bool RELU>
__global__ __launch_bounds__(512) void gemm_bias(
        const __half* __restrict__ Ahi, const __half* __restrict__ Alo,
        const __half* __restrict__ W,
        const float* __restrict__ bias,
        float* __restrict__ outF,
        __half* __restrict__ outH1, __half* __restrict__ outH2,
        int N) {
    gemm_body<K, OM, RELU>(Ahi, Alo, W, bias, outF, outH1, outH2, 1.f,
                           N, blockIdx.x*128, blockIdx.y*64);
}

// Fused QKV: grid (126, 6); writes fp16 (Q pre-scaled by SCALE*log2e)
__global__ __launch_bounds__(512) void gemm_qkv(int layer) {
    int sel = blockIdx.y >> 1;
    int col0 = (blockIdx.y & 1) * 64;
    const __half* W = g_qkvw + ((size_t)(layer*3 + sel))*Dd*128;
    const float* bias = g_qkvb + (layer*3 + sel)*128;
    __half* oh = g_qkv + (size_t)sel*BLd*128;
    float oscale = (sel == 0) ? SC2f : 1.f;
    gemm_body<256, 2, false>(g_hh, g_hl, W, bias, nullptr, oh, nullptr, oscale,
                             128, blockIdx.x*128, col0);
}

// ---------------------------------------------------------------------------
// GEMM (tile 128 x 256, full rows) + fused residual + LayerNorm.
// Residual read from split fp16 (hh+hl); writes split fp16 only.
// ---------------------------------------------------------------------------
#define LNSS 260

template<int K>
__global__ __launch_bounds__(512) void gemm_ln(
        const __half* __restrict__ Ahi,
        const __half* __restrict__ Alo,
        const __half* __restrict__ W,
        const float* __restrict__ bias,
        const float* __restrict__ gam,
        const float* __restrict__ bet) {
    extern __shared__ __half smh[];
    constexpr int SA = K + 8;
    __half* sAh = smh;
    __half* sAl = smh + 128 * SA;
    __half* sW  = smh + 256 * SA;
    float* sv = (float*)smh;

    const int tid = threadIdx.x, lane = tid & 31, warp = tid >> 5;
    const int row0 = blockIdx.x * 128;

    constexpr int AV = K / 8;
    #pragma unroll 2
    for (int i = tid; i < 128 * AV; i += 512) {
        int r = i / AV, c = (i % AV) * 8;
        size_t g = (size_t)(row0 + r)*K + c;
        *reinterpret_cast<uint4*>(&sAh[r*SA + c]) = *reinterpret_cast<const uint4*>(&Ahi[g]);
        *reinterpret_cast<uint4*>(&sAl[r*SA + c]) = *reinterpret_cast<const uint4*>(&Alo[g]);
    }
    #pragma unroll 2
    for (int i = tid; i < 256 * K / 4; i += 512) {
        int k = i / 64, n4 = (i % 64) * 4;
        size_t g = (size_t)k*Dd + n4;
        uint2 w2 = *reinterpret_cast<const uint2*>(&W[g]);
        __half tw[4]; *reinterpret_cast<uint2*>(tw) = w2;
        #pragma unroll
        for (int j = 0; j < 4; j++) sW[(n4+j)*SA + k] = tw[j];
    }
    __syncthreads();

    float acc[16][4];
    #pragma unroll
    for (int i = 0; i < 16; i++)
        #pragma unroll
        for (int j = 0; j < 4; j++) acc[i][j] = 0.f;

    const int mwarp = warp >> 1, nwarp = warp & 1;
    const int ar = mwarp*16 + (lane >> 2);
    const int ac = (lane & 3) * 2;
    #pragma unroll
    for (int kk = 0; kk < K/16; kk++) {
        uint32_t ah[4], al[4];
        {
            const __half* pa = &sAh[ar*SA + kk*16 + ac];
            ah[0] = *(const uint32_t*)pa;
            ah[1] = *(const uint32_t*)(pa + 8*SA);
            ah[2] = *(const uint32_t*)(pa + 8);
            ah[3] = *(const uint32_t*)(pa + 8*SA + 8);
            const __half* pl = &sAl[ar*SA + kk*16 + ac];
            al[0] = *(const uint32_t*)pl;
            al[1] = *(const uint32_t*)(pl + 8*SA);
            al[2] = *(const uint32_t*)(pl + 8);
            al[3] = *(const uint32_t*)(pl + 8*SA + 8);
        }
        #pragma unroll
        for (int nt = 0; nt < 16; nt++) {
            int nrow = nwarp*128 + nt*8 + (lane>>2);
            const __half* pb = &sW[nrow*SA + kk*16 + ac];
            uint32_t b0 = *(const uint32_t*)pb;
            uint32_t b1 = *(const uint32_t*)(pb + 8);
            mma16816h(acc[nt], ah, b0, b1);
            mma16816h(acc[nt], al, b0, b1);
        }
    }
    __syncthreads();

    {
        const int r0 = mwarp*16 + (lane >> 2);
        #pragma unroll
        for (int nt = 0; nt < 16; nt++) {
            int c = nwarp*128 + nt*8 + (lane & 3)*2;
            float b0v = bias[c], b1v = bias[c+1];
            sv[ r0     *LNSS + c]     = acc[nt][0] + b0v;
            sv[ r0     *LNSS + c + 1] = acc[nt][1] + b1v;
            sv[(r0 + 8)*LNSS + c]     = acc[nt][2] + b0v;
            sv[(r0 + 8)*LNSS + c + 1] = acc[nt][3] + b1v;
        }
    }
    __syncthreads();

    #pragma unroll 1
    for (int rr = 0; rr < 8; rr++) {
        int row = warp*8 + rr;
        int token = row0 + row;
        const __half* hph = &g_hh[(size_t)token*Dd];
        const __half* hpl = &g_hl[(size_t)token*Dd];
        float x[8], s = 0.f;
        #pragma unroll
        for (int j = 0; j < 8; j++) {
            int cix = lane*8 + j;
            x[j] = __half2float(hph[cix]) + __half2float(hpl[cix])
                 + sv[row*LNSS + cix];
            s += x[j];
        }
        #pragma unroll
        for (int o = 16; o; o >>= 1) s += __shfl_xor_sync(~0u, s, o);
        float mean = s * (1.f/256.f);
        float v = 0.f;
        #pragma unroll
        for (int j = 0; j < 8; j++) { float d = x[j] - mean; v += d*d; }
        #pragma unroll
        for (int o = 16; o; o >>= 1) v += __shfl_xor_sync(~0u, v, o);
        float rstd = rsqrtf(v * (1.f/256.f) + EPSLN);
        #pragma unroll
        for (int j = 0; j < 8; j++) {
            int cix = lane*8 + j;
            float y = (x[j] - mean)*rstd*gam[cix] + bet[cix];
            size_t ix = (size_t)token*Dd + cix;
            fsplit_h(y, g_hh[ix], g_hl[ix]);
        }
    }
}

// ---------------------------------------------------------------------------
// Attention (fp16, R12 configuration): 128-query tile, 256 threads (8 warps
// x 16 rows). Single-term fp16 MMA (Q pre-scaled by SCALE*log2e in QKV GEMM).
// Pass A: row sums (4-buffer K ring, 2 chunks/barrier). Pass B: QK (SW
// pipelined), P out (.cs), PV. smem 40KB -> 3 CTAs/SM.
// Zfilled padding keys -> score exactly 0 -> exp exactly 1 -> subtract 32.
// ---------------------------------------------------------------------------
#define QT 128
#define KT 128
#define NCH 16
#define NPAD 32.0f

#define BUFB 10240                 // bytes per 128x40-half buffer
#define SM_ATTN_BYTES (4*BUFB)     // 40960

__device__ __forceinline__ void stage1(uint32_t sm_u, int bufoff, int ch,
        const __half* P, size_t base, int tid) {
    const int k0 = ch * KT;
    #pragma unroll
    for (int it = 0; it < 2; it++) {
        int o = tid + it*256;
        int r = o >> 2;
        int c = (o & 3) * 8;
        int s = k0 + r;
        bool ok = s < Ld;
        const __half* src = P + base + (size_t)(ok ? s : 0)*128 + c;
        uint32_t dst = sm_u + bufoff + (r*40 + c)*2;
        cpa16(dst, src, ok ? 16 : 0);
    }
}

__device__ __forceinline__ void qk_stats_chunk(
        uint32_t kh_u, int laneK,
        const uint32_t aq[2][4],
        float& s0, float& s1) {
    #pragma unroll 2
    for (int gq = 0; gq < 4; gq++) {
        float acc[4][4];
        #pragma unroll
        for (int i = 0; i < 4; i++)
            #pragma unroll
            for (int j = 0; j < 4; j++) acc[i][j] = 0.f;
        #pragma unroll
        for (int pair = 0; pair < 2; pair++) {
            int be = (gq*32 + pair*16)*40;
            #pragma unroll
            for (int kk = 0; kk < 2; kk++) {
                uint32_t b0, b1, b2, b3;
                uint32_t off = (be + kk*16 + laneK)*2;
                ldsm4(b0, b1, b2, b3, kh_u + off);
                mma16816h(acc[pair*2  ], aq[kk], b0, b1);
                mma16816h(acc[pair*2+1], aq[kk], b2, b3);
            }
        }
        #pragma unroll
        for (int nt = 0; nt < 4; nt++) {
            s0 += ex2(acc[nt][0]) + ex2(acc[nt][1]);
            s1 += ex2(acc[nt][2]) + ex2(acc[nt][3]);
        }
    }
}

__device__ __forceinline__ void qk_group(
        uint32_t kh_u, int laneK, int kbe,
        const uint32_t aq[2][4], float acc[2][4]) {
    #pragma unroll
    for (int i = 0; i < 2; i++)
        #pragma unroll
        for (int j = 0; j < 4; j++) acc[i][j] = 0.f;
    #pragma unroll
    for (int kk = 0; kk < 2; kk++) {
        uint32_t b0, b1, b2, b3;
        uint32_t off = (kbe + kk*16 + laneK)*2;
        ldsm4(b0, b1, b2, b3, kh_u + off);
        mma16816h(acc[0], aq[kk], b0, b1);
        mma16816h(acc[1], aq[kk], b2, b3);
    }
}

template<bool MASK>
__device__ __forceinline__ void emit_group(
        uint32_t vh_u, int laneV, int g, int k0, int fc,
        float inv0, float inv1,
        float* prow0, float* prow1, bool wr0, bool wr1,
        const float acc[2][4], float oacc[4][4]) {
    int kbe = g*16*40;
    int colb = k0 + g*16 + fc;
    bool ok0 = !MASK || (colb < Ld);
    bool ok1 = !MASK || (colb + 8 < Ld);
    float p00 = ok0 ? ex2(acc[0][0])*inv0 : 0.f;
    float p01 = ok0 ? ex2(acc[0][1])*inv0 : 0.f;
    float p02 = ok0 ? ex2(acc[0][2])*inv1 : 0.f;
    float p03 = ok0 ? ex2(acc[0][3])*inv1 : 0.f;
    float p10 = ok1 ? ex2(acc[1][0])*inv0 : 0.f;
    float p11 = ok1 ? ex2(acc[1][1])*inv0 : 0.f;
    float p12 = ok1 ? ex2(acc[1][2])*inv1 : 0.f;
    float p13 = ok1 ? ex2(acc[1][3])*inv1 : 0.f;

    if (wr0) {
        if (ok0) stcs2(&prow0[colb],     p00, p01);
        if (ok1) stcs2(&prow0[colb + 8], p10, p11);
    }
    if (wr1) {
        if (ok0) stcs2(&prow1[colb],     p02, p03);
        if (ok1) stcs2(&prow1[colb + 8], p12, p13);
    }

    uint32_t ah[4];
    ah[0] = pk2h(p00, p01);
    ah[1] = pk2h(p02, p03);
    ah[2] = pk2h(p10, p11);
    ah[3] = pk2h(p12, p13);

    #pragma unroll
    for (int dp = 0; dp < 2; dp++) {
        uint32_t v0, v1, v2, v3;
        uint32_t off = (kbe + dp*16 + laneV)*2;
        ldsm4t(v0, v1, v2, v3, vh_u + off);
        mma16816h(oacc[dp*2  ], ah, v0, v1);
        mma16816h(oacc[dp*2+1], ah, v2, v3);
    }
}

template<bool MASK>
__device__ __forceinline__ void qk_emit_chunk(
        uint32_t kh_u, uint32_t vh_u, int laneK, int laneV,
        const uint32_t aq[2][4],
        int k0, int fc, float inv0, float inv1,
        float* prow0, float* prow1, bool wr0, bool wr1,
        float oacc[4][4]) {
    float aA[2][4], aB[2][4];
    qk_group(kh_u, laneK, 0, aq, aA);
    #pragma unroll
    for (int g = 0; g < 8; g += 2) {
        qk_group(kh_u, laneK, (g+1)*640, aq, aB);
        emit_group<MASK>(vh_u, laneV, g, k0, fc, inv0, inv1,
                         prow0, prow1, wr0, wr1, aA, oacc);
        if (g + 2 < 8)
            qk_group(kh_u, laneK, (g+2)*640, aq, aA);
        emit_group<MASK>(vh_u, laneV, g+1, k0, fc, inv0, inv1,
                         prow0, prow1, wr0, wr1, aB, oacc);
    }
}

__global__ __launch_bounds__(256, 3) void attn_kernel(
        const __half* __restrict__ qkv,
        float* __restrict__ Pout,
        __half* __restrict__ Oh, __half* __restrict__ Ol) {
    extern __shared__ __half smh[];
    uint32_t sm_u = (uint32_t)__cvta_generic_to_shared(smh);

    const int tid = threadIdx.x, lane = tid & 31, warp = tid >> 5;
    const int bh = blockIdx.y;
    const int b  = bh >> 2, h = bh & 3;
    const int q0 = blockIdx.x * QT;
    const size_t base = ((size_t)b*Ld*Hd + h)*DKd;
    const __half* Q = qkv;
    const __half* K = qkv + (size_t)BLd*128;
    const __half* V = qkv + (size_t)2*BLd*128;

    const int mrow = warp * 16;
    const int fr = lane >> 2, fc = (lane & 3) * 2;
    const int lr = lane & 7, sel = lane >> 3;
    const int laneK = ((sel>>1)*8 + lr)*40 + (sel&1)*8;
    const int laneV = ((sel&1)*8 + lr)*40 + (sel>>1)*8;

    const int r0g = q0 + mrow + fr, r1g = r0g + 8;
    const bool q0ok = (r0g < Ld), q1ok = (r1g < Ld);
    uint32_t aq[2][4];
    #pragma unroll
    for (int kk = 0; kk < 2; kk++) {
        int c = kk*16 + fc;
        size_t g0 = base + (size_t)r0g*128 + c;
        size_t g1 = base + (size_t)r1g*128 + c;
        aq[kk][0] = q0ok ? *(const uint32_t*)&Q[g0]     : 0;
        aq[kk][1] = q1ok ? *(const uint32_t*)&Q[g1]     : 0;
        aq[kk][2] = q0ok ? *(const uint32_t*)&Q[g0 + 8] : 0;
        aq[kk][3] = q1ok ? *(const uint32_t*)&Q[g1 + 8] : 0;
    }

    float s0 = 0.f, s1 = 0.f;

    // ======== PASS A: row sums (K only, 4-buffer ring, 2 chunks/sync) ====
    stage1(sm_u, 0*BUFB, 0, K, base, tid);
    stage1(sm_u, 1*BUFB, 1, K, base, tid); cpa_commit();
    stage1(sm_u, 2*BUFB, 2, K, base, tid);
    stage1(sm_u, 3*BUFB, 3, K, base, tid); cpa_commit();
    #pragma unroll 1
    for (int it = 0; it < 8; it++) {
        if (it < 7) cpa_wait<1>(); else cpa_wait<0>();
        __syncthreads();
        int b0 = (it & 1) ? 2 : 0;
        qk_stats_chunk(sm_u + b0*BUFB,     laneK, aq, s0, s1);
        qk_stats_chunk(sm_u + (b0+1)*BUFB, laneK, aq, s0, s1);
        __syncthreads();
        if (it < 6) {
            stage1(sm_u, b0*BUFB,     2*it+4, K, base, tid);
            stage1(sm_u, (b0+1)*BUFB, 2*it+5, K, base, tid);
            cpa_commit();
        }
    }

    // prologue for pass B overlaps the reduction: K in bufs 0/1, V in 2/3
    stage1(sm_u, 0*BUFB, 0, K, base, tid);
    stage1(sm_u, 2*BUFB, 0, V, base, tid); cpa_commit();
    stage1(sm_u, 1*BUFB, 1, K, base, tid);
    stage1(sm_u, 3*BUFB, 1, V, base, tid); cpa_commit();

    s0 += __shfl_xor_sync(~0u, s0, 1);
    s0 += __shfl_xor_sync(~0u, s0, 2);
    s1 += __shfl_xor_sync(~0u, s1, 1);
    s1 += __shfl_xor_sync(~0u, s1, 2);
    s0 -= NPAD;
    s1 -= NPAD;
    const float inv0 = 1.f / s0, inv1 = 1.f / s1;

    // ======== PASS B: P out + PV ========
    float oacc[4][4];
    #pragma unroll
    for (int i = 0; i < 4; i++)
        #pragma unroll
        for (int j = 0; j < 4; j++) oacc[i][j] = 0.f;

    float* prow0 = &Pout[((size_t)bh*Ld + r0g)*Ld];
    float* prow1 = prow0 + 8*(size_t)Ld;

    #pragma unroll 1
    for (int ch = 0; ch < NCH; ch++) {
        if (ch < NCH-1) cpa_wait<1>(); else cpa_wait<0>();
        __syncthreads();
        int buf = ch & 1;
        uint32_t kh_u = sm_u + buf*BUFB;
        uint32_t vh_u = sm_u + (2 + buf)*BUFB;
        if (ch < NCH-1)
            qk_emit_chunk<false>(kh_u, vh_u, laneK, laneV, aq,
                                 ch*KT, fc, inv0, inv1, prow0, prow1, q0ok, q1ok, oacc);
        else
            qk_emit_chunk<true >(kh_u, vh_u, laneK, laneV, aq,
                                 ch*KT, fc, inv0, inv1, prow0, prow1, q0ok, q1ok, oacc);
        __syncthreads();
        if (ch + 2 < NCH) {
            stage1(sm_u, buf*BUFB,       ch+2, K, base, tid);
            stage1(sm_u, (2 + buf)*BUFB, ch+2, V, base, tid);
            cpa_commit();
        }
    }

    // ---- write O (split fp16) ----
    #pragma unroll
    for (int dt = 0; dt < 4; dt++) {
        int d = dt*8 + fc;
        if (q0ok) {
            size_t g = base + (size_t)r0g*128 + d;
            __half hh, ll;
            fsplit_h(oacc[dt][0], hh, ll); Oh[g]   = hh; Ol[g]   = ll;
            fsplit_h(oacc[dt][1], hh, ll); Oh[g+1] = hh; Ol[g+1] = ll;
        }
        if (q1ok) {
            size_t g = base + (size_t)r1g*128 + d;
            __half hh, ll;
            fsplit_h(oacc[dt][2], hh, ll); Oh[g]   = hh; Ol[g]   = ll;
            fsplit_h(oacc[dt][3], hh, ll); Oh[g+1] = hh; Ol[g+1] = ll;
        }
    }
}

// ---------------------------------------------------------------------------
// Final head tail: out = relu_h(g_tmp fp32) @ o2w + o2b   (warp per token)
// ---------------------------------------------------------------------------
__global__ __launch_bounds__(256) void head2_kernel(const float* __restrict__ o2w,
                                                    const float* __restrict__ o2b,
                                                    float* __restrict__ out) {
    int warp = threadIdx.x >> 5, lane = threadIdx.x & 31;
    int token = blockIdx.x * 8 + warp;
    const float* hp = &g_tmp[(size_t)token*Dd];
    float a0 = 0.f, a1 = 0.f;
    #pragma unroll
    for (int j = 0; j < 8; j++) {
        int k = lane + j*32;
        float hv = hp[k];
        a0 = fmaf(hv, o2w[k*2],   a0);
        a1 = fmaf(hv, o2w[k*2+1], a1);
    }
    #pragma unroll
    for (int o = 16; o; o >>= 1) {
        a0 += __shfl_xor_sync(~0u, a0, o);
        a1 += __shfl_xor_sync(~0u, a1, o);
    }
    if (lane == 0) {
        out[(size_t)token*2]     = a0 + o2b[0];
        out[(size_t)token*2 + 1] = a1 + o2b[1];
    }
}

// ---------------------------------------------------------------------------
// Host orchestration
// ---------------------------------------------------------------------------
static inline void* symaddr(const void* s) {
    void* p = nullptr;
    cudaGetSymbolAddress(&p, s);
    return p;
}

extern "C" void kernel_launch(void* const* d_in, const int* in_sizes, int n_in,
                              void* d_out, int out_size) {
    const float* x    = (const float*)d_in[0];
    const float* in_w = (const float*)d_in[1];
    const float* in_b = (const float*)d_in[2];
    const float* qw   = (const float*)d_in[3];
    const float* qb   = (const float*)d_in[4];
    const float* kw   = (const float*)d_in[5];
    const float* kb   = (const float*)d_in[6];
    const float* vw   = (const float*)d_in[7];
    const float* vb   = (const float*)d_in[8];
    const float* ow   = (const float*)d_in[9];
    const float* ob   = (const float*)d_in[10];
    const float* f1w  = (const float*)d_in[11];
    const float* f1b  = (const float*)d_in[12];
    const float* f2w  = (const float*)d_in[13];
    const float* f2b  = (const float*)d_in[14];
    const float* n1g  = (const float*)d_in[15];
    const float* n1b  = (const float*)d_in[16];
    const float* n2g  = (const float*)d_in[17];
    const float* n2b  = (const float*)d_in[18];
    const float* o1w  = (const float*)d_in[19];
    const float* o1b  = (const float*)d_in[20];
    const float* o2w  = (const float*)d_in[21];
    const float* o2b  = (const float*)d_in[22];

    float* outp     = (float*)d_out;
    float* attn_out = outp + (size_t)Bd*Ld*2;

    __half* p_hh   = (__half*)symaddr(g_hh);
    __half* p_hl   = (__half*)symaddr(g_hl);
    __half* p_qkv  = (__half*)symaddr(g_qkv);
    __half* p_oh   = (__half*)symaddr(g_oh);
    __half* p_ol   = (__half*)symaddr(g_ol);
    __half* p_fh   = (__half*)symaddr(g_fh);
    __half* p_fl   = (__half*)symaddr(g_fl);
    float*  p_tmp  = (float*)symaddr(g_tmp);
    __half* p_ow   = (__half*)symaddr(g_ow);
    __half* p_f1w  = (__half*)symaddr(g_f1w);
    __half* p_f2w  = (__half*)symaddr(g_f2w);
    __half* p_o1w  = (__half*)symaddr(g_o1w);

    const int SM_G256  = (2*128*(256+8) + 64*(256+8))*2;      // 168960
    const int SM_LN128 = (2*128*(128+8) + 256*(128+8))*2;     // 139264
    const int SM_LN64_OP = (2*128*(64+8) + 256*(64+8))*2;     // 73728
    const int SM_LNSLAB  = 128*LNSS*4;                        // 133120
    const int SM_LN64  = SM_LN64_OP > SM_LNSLAB ? SM_LN64_OP : SM_LNSLAB;
    const int SM_LN128F = SM_LN128 > SM_LNSLAB ? SM_LN128 : SM_LNSLAB;

    cudaFuncSetAttribute(gemm_qkv, cudaFuncAttributeMaxDynamicSharedMemorySize, SM_G256);
    cudaFuncSetAttribute(gemm_bias<256,1,true >, cudaFuncAttributeMaxDynamicSharedMemorySize, SM_G256);
    cudaFuncSetAttribute(gemm_bias<256,0,true >, cudaFuncAttributeMaxDynamicSharedMemorySize, SM_G256);
    cudaFuncSetAttribute(gemm_ln<128>, cudaFuncAttributeMaxDynamicSharedMemorySize, SM_LN128F);
    cudaFuncSetAttribute(gemm_ln<64 >, cudaFuncAttributeMaxDynamicSharedMemorySize, SM_LN64);
    cudaFuncSetAttribute(attn_kernel, cudaFuncAttributeMaxDynamicSharedMemorySize, SM_ATTN_BYTES);

    convert_w<<<384, 256>>>(qw, kw, vw, ow, f1w, f2w, o1w, qb, kb, vb);
    embed_kernel<<<BLd, Dd>>>(x, in_w, in_b);

    const dim3 gQKV (BLd/128, 6);
    const dim3 gProj(BLd/128, 4);   // N=256 (head only)
    const dim3 gF1  (BLd/128, 1);   // N=64
    const dim3 gLN  (BLd/128);
    const dim3 gAttn((Ld + QT - 1)/QT, Bd*Hd);

    for (int i = 0; i < NLd; i++) {
        gemm_qkv<<<gQKV, 512, SM_G256>>>(i);

        attn_kernel<<<gAttn, 256, SM_ATTN_BYTES>>>(
            p_qkv, attn_out + (size_t)i*Bd*Hd*Ld*Ld, p_oh, p_ol);

        // o-projection + residual + LN1 (fused)
        gemm_ln<128><<<gLN, 512, SM_LN128F>>>(
            p_oh, p_ol, p_ow + (size_t)i*128*Dd,
            ob + i*Dd, n1g + i*Dd, n1b + i*Dd);

        // FFN1 (relu, split fp16 out)
        gemm_bias<256,1,true><<<gF1, 512, SM_G256>>>(
            p_hh, p_hl, p_f1w + (size_t)i*Dd*FCd,
            f1b + i*FCd, nullptr, p_fh, p_fl, FCd);

        // FFN2 + residual + LN2 (fused)
        gemm_ln<64><<<gLN, 512, SM_LN64>>>(
            p_fh, p_fl, p_f2w + (size_t)i*FCd*Dd,
            f2b + i*Dd, n2g + i*Dd, n2b + i*Dd);
    }

    gemm_bias<256,0,true><<<gProj, 512, SM_G256>>>(
        p_hh, p_hl, p_o1w, o1b, p_tmp, nullptr, nullptr, Dd);
    head2_kernel<<<BLd/8, 256>>>(o2w, o2b, outp);
}

// round 16
// speedup vs baseline: 1.4989x; 1.0394x over previous
#include <cuda_runtime.h>
#include <cuda_bf16.h>
#include <cuda_fp16.h>
#include <stdint.h>

#define Bd  8
#define Ld  2016
#define Hd  4
#define DKd 32
#define Dd  256
#define FCd 64
#define NLd 3
#define BLd (Bd*Ld)          // 16128 tokens

#define SC2f 0.09016844005556f   // (1/sqrt(256)) * log2(e)
#define EPSLN 1e-5f

// ---------------------------------------------------------------------------
// Device scratch. Residual stream: split fp16 only. Weights: fp16.
// ---------------------------------------------------------------------------
__device__ __align__(128) __half  g_hh   [BLd*Dd];
__device__ __align__(128) __half  g_hl   [BLd*Dd];
__device__ __align__(128) __half  g_qkv  [3*BLd*128];   // fp16 (Q pre-scaled)
__device__ __align__(128) __half  g_oh   [BLd*128];
__device__ __align__(128) __half  g_ol   [BLd*128];
__device__ __align__(128) float   g_tmp  [BLd*Dd];
// fp16 weights
__device__ __align__(128) __half  g_qkvw [NLd*3*Dd*128];
__device__ __align__(128) float   g_qkvb [NLd*3*128];
__device__ __align__(128) __half  g_ow   [NLd*128*Dd];
__device__ __align__(128) __half  g_f1w  [NLd*Dd*FCd];
__device__ __align__(128) __half  g_f2w  [NLd*FCd*Dd];
__device__ __align__(128) __half  g_o1w  [Dd*Dd];

// ---------------------------------------------------------------------------
// helpers
// ---------------------------------------------------------------------------
__device__ __forceinline__ void mma16816h(float* d, const uint32_t* a,
                                          uint32_t b0, uint32_t b1) {
    asm volatile(
        "mma.sync.aligned.m16n8k16.row.col.f32.f16.f16.f32 "
        "{%0,%1,%2,%3}, {%4,%5,%6,%7}, {%8,%9}, {%0,%1,%2,%3};"
        : "+f"(d[0]), "+f"(d[1]), "+f"(d[2]), "+f"(d[3])
        : "r"(a[0]), "r"(a[1]), "r"(a[2]), "r"(a[3]), "r"(b0), "r"(b1));
}

__device__ __forceinline__ void ldsm4(uint32_t& r0, uint32_t& r1,
                                      uint32_t& r2, uint32_t& r3, uint32_t a) {
    asm volatile("ldmatrix.sync.aligned.m8n8.x4.shared.b16 {%0,%1,%2,%3}, [%4];"
        : "=r"(r0), "=r"(r1), "=r"(r2), "=r"(r3) : "r"(a));
}

__device__ __forceinline__ void ldsm4t(uint32_t& r0, uint32_t& r1,
                                       uint32_t& r2, uint32_t& r3, uint32_t a) {
    asm volatile("ldmatrix.sync.aligned.m8n8.x4.trans.shared.b16 {%0,%1,%2,%3}, [%4];"
        : "=r"(r0), "=r"(r1), "=r"(r2), "=r"(r3) : "r"(a));
}

__device__ __forceinline__ void cpa16(uint32_t dst, const void* src, int srcsize) {
    asm volatile("cp.async.cg.shared.global [%0], [%1], 16, %2;"
        :: "r"(dst), "l"(src), "r"(srcsize));
}
__device__ __forceinline__ void cpa_commit() {
    asm volatile("cp.async.commit_group;" ::: "memory");
}
template<int N>
__device__ __forceinline__ void cpa_wait() {
    asm volatile("cp.async.wait_group %0;" :: "n"(N) : "memory");
}

__device__ __forceinline__ float ex2(float x) {
    float y;
    asm("ex2.approx.ftz.f32 %0, %1;" : "=f"(y) : "f"(x));
    return y;
}

__device__ __forceinline__ uint32_t pk2h(float x, float y) {
    __half2 t = __floats2half2_rn(x, y);
    return *reinterpret_cast<uint32_t*>(&t);
}

__device__ __forceinline__ void fsplit_h(float v, __half& hi, __half& lo) {
    hi = __float2half_rn(v);
    lo = __float2half_rn(v - __half2float(hi));
}

__device__ __forceinline__ void stcs2(float* p, float a, float b) {
    asm volatile("st.global.cs.v2.f32 [%0], {%1,%2};" :: "l"(p), "f"(a), "f"(b));
}

// ---------------------------------------------------------------------------
// Weight conversion fp32 -> fp16 (+ QKV packing)
// ---------------------------------------------------------------------------
__global__ void convert_w(const float* __restrict__ qw, const float* __restrict__ kw,
                          const float* __restrict__ vw, const float* __restrict__ ow,
                          const float* __restrict__ f1w, const float* __restrict__ f2w,
                          const float* __restrict__ o1w,
                          const float* __restrict__ qb, const float* __restrict__ kb,
                          const float* __restrict__ vb) {
    int i = blockIdx.x * 256 + threadIdx.x;
    const int n1 = NLd*Dd*128;
    const int n3 = NLd*Dd*FCd;
    const int n5 = Dd*Dd;
    if (i < n1) {
        int l = i / (Dd*128), rem = i % (Dd*128);
        size_t b = (size_t)(l*3)*Dd*128 + rem;
        g_qkvw[b]            = __float2half_rn(qw[i]);
        g_qkvw[b + Dd*128]   = __float2half_rn(kw[i]);
        g_qkvw[b + 2*Dd*128] = __float2half_rn(vw[i]);
        g_ow[i]              = __float2half_rn(ow[i]);
    }
    if (i < n3) {
        g_f1w[i] = __float2half_rn(f1w[i]);
        g_f2w[i] = __float2half_rn(f2w[i]);
    }
    if (i < n5) g_o1w[i] = __float2half_rn(o1w[i]);
    if (i < NLd*128) {
        int l = i >> 7, n = i & 127;
        g_qkvb[(l*3+0)*128 + n] = qb[i];
        g_qkvb[(l*3+1)*128 + n] = kb[i];
        g_qkvb[(l*3+2)*128 + n] = vb[i];
    }
}

// ---------------------------------------------------------------------------
// Embed: h = x @ in_w + in_b (split fp16)
// ---------------------------------------------------------------------------
__global__ void embed_kernel(const float* __restrict__ x,
                             const float* __restrict__ in_w,
                             const float* __restrict__ in_b) {
    int t = blockIdx.x, d = threadIdx.x;
    float x0 = x[t*2], x1 = x[t*2+1];
    float v = fmaf(x0, in_w[d], fmaf(x1, in_w[Dd + d], in_b[d]));
    size_t ix = (size_t)t*Dd + d;
    fsplit_h(v, g_hh[ix], g_hl[ix]);
}

// ---------------------------------------------------------------------------
// GEMM core: tile 128x64, 512 threads. 2-term split fp16 MMA
// (A = hi+lo fp16, W = single fp16). OM: 0=fp32, 2=fp16*scale.
// ---------------------------------------------------------------------------
template<int K, int OM, bool RELU>
__device__ __forceinline__ void gemm_body(
        const __half* __restrict__ Ahi,
        const __half* __restrict__ Alo,
        const __half* __restrict__ W,
        const float* __restrict__ bias,
        float* __restrict__ outF,
        __half* __restrict__ outH1, float oscale,
        int N, int row0, int col0) {
    extern __shared__ __half smh[];
    constexpr int SA = K + 8;
    __half* sAh = smh;
    __half* sAl = smh + 128 * SA;
    __half* sW  = smh + 256 * SA;

    const int tid = threadIdx.x, lane = tid & 31, warp = tid >> 5;

    constexpr int AV = K / 8;
    #pragma unroll 2
    for (int i = tid; i < 128 * AV; i += 512) {
        int r = i / AV, c = (i % AV) * 8;
        size_t g = (size_t)(row0 + r)*K + c;
        *reinterpret_cast<uint4*>(&sAh[r*SA + c]) = *reinterpret_cast<const uint4*>(&Ahi[g]);
        *reinterpret_cast<uint4*>(&sAl[r*SA + c]) = *reinterpret_cast<const uint4*>(&Alo[g]);
    }
    #pragma unroll 2
    for (int i = tid; i < 64 * K / 4; i += 512) {
        int k = i >> 4, n4 = (i & 15) * 4;
        size_t g = (size_t)k*N + col0 + n4;
        uint2 w2 = *reinterpret_cast<const uint2*>(&W[g]);
        __half tw[4]; *reinterpret_cast<uint2*>(tw) = w2;
        #pragma unroll
        for (int j = 0; j < 4; j++) sW[(n4+j)*SA + k] = tw[j];
    }
    __syncthreads();

    float acc[4][4];
    #pragma unroll
    for (int i = 0; i < 4; i++)
        #pragma unroll
        for (int j = 0; j < 4; j++) acc[i][j] = 0.f;

    const int mwarp = warp >> 1, nwarp = warp & 1;
    const int ar = mwarp*16 + (lane >> 2);
    const int ac = (lane & 3) * 2;
    #pragma unroll
    for (int kk = 0; kk < K/16; kk++) {
        uint32_t ah[4], al[4];
        {
            const __half* pa = &sAh[ar*SA + kk*16 + ac];
            ah[0] = *(const uint32_t*)pa;
            ah[1] = *(const uint32_t*)(pa + 8*SA);
            ah[2] = *(const uint32_t*)(pa + 8);
            ah[3] = *(const uint32_t*)(pa + 8*SA + 8);
            const __half* pl = &sAl[ar*SA + kk*16 + ac];
            al[0] = *(const uint32_t*)pl;
            al[1] = *(const uint32_t*)(pl + 8*SA);
            al[2] = *(const uint32_t*)(pl + 8);
            al[3] = *(const uint32_t*)(pl + 8*SA + 8);
        }
        #pragma unroll
        for (int nt = 0; nt < 4; nt++) {
            int nrow = nwarp*32 + nt*8 + (lane>>2);
            const __half* pb = &sW[nrow*SA + kk*16 + ac];
            uint32_t b0 = *(const uint32_t*)pb;
            uint32_t b1 = *(const uint32_t*)(pb + 8);
            mma16816h(acc[nt], ah, b0, b1);
            mma16816h(acc[nt], al, b0, b1);
        }
    }

    const int orow = row0 + mwarp*16 + (lane >> 2);
    #pragma unroll
    for (int nt = 0; nt < 4; nt++) {
        int c = col0 + nwarp*32 + nt*8 + (lane & 3)*2;
        float b0v = bias[c], b1v = bias[c+1];
        #pragma unroll
        for (int half = 0; half < 2; half++) {
            int r = orow + half*8;
            float v0 = acc[nt][half*2+0] + b0v;
            float v1 = acc[nt][half*2+1] + b1v;
            if (RELU) { v0 = fmaxf(v0, 0.f); v1 = fmaxf(v1, 0.f); }
            size_t o = (size_t)r*N + c;
            if (OM == 0) { outF[o] = v0; outF[o+1] = v1; }
            if (OM == 2) {
                __half2 t = __floats2half2_rn(v0*oscale, v1*oscale);
                *reinterpret_cast<__half2*>(&outH1[o]) = t;
            }
        }
    }
}

template<int K, int OM, bool RELU>
__global__ __launch_bounds__(512) void gemm_bias(
        const __half* __restrict__ Ahi, const __half* __restrict__ Alo,
        const __half* __restrict__ W,
        const float* __restrict__ bias,
        float* __restrict__ outF, __half* __restrict__ outH1,
        int N) {
    gemm_body<K, OM, RELU>(Ahi, Alo, W, bias, outF, outH1, 1.f,
                           N, blockIdx.x*128, blockIdx.y*64);
}

// Fused QKV: grid (126, 6); writes fp16 (Q pre-scaled by SCALE*log2e)
__global__ __launch_bounds__(512) void gemm_qkv(int layer) {
    int sel = blockIdx.y >> 1;
    int col0 = (blockIdx.y & 1) * 64;
    const __half* W = g_qkvw + ((size_t)(layer*3 + sel))*Dd*128;
    const float* bias = g_qkvb + (layer*3 + sel)*128;
    __half* oh = g_qkv + (size_t)sel*BLd*128;
    float oscale = (sel == 0) ? SC2f : 1.f;
    gemm_body<256, 2, false>(g_hh, g_hl, W, bias, nullptr, oh, oscale,
                             128, blockIdx.x*128, col0);
}

// ---------------------------------------------------------------------------
// Fused layer tail: per 128 rows, one CTA does
//   v  = O @ Wo + ob          (K=128)
//   h1 = LN1(h_prev + v)      (in smem, split fp16 A-layout)
//   f  = relu(h1 @ W1 + f1b)  (K=256)
//   x  = h1 + f @ W2 + f2b    (K=64, RMW in smem)
//   h  = LN2(x) -> g_hh/g_hl
// 512 threads (16 warps = 8 M x 2 N). smem 204KB, 1 CTA/SM, grid 126.
// smem (halves): H hi [0,33792) lo [33792,67584), SA_H=264
//   ph0 O tile overlaps H: Ohi [0,17408) Olo [17408,34816), SA_O=136
//   Wo  [67584,102400) (256x136)
//   W1  [67584, 84480) (64x264)   (after ph0)
//   f   hi [67584,76800) lo [76800,86016) (128x72 each, after ph1 MMA)
//   W2  [86016,104448) (256x72)
// ---------------------------------------------------------------------------
#define SM_TAIL_BYTES 208896

__global__ __launch_bounds__(512, 1) void fused_tail(
        const __half* __restrict__ Ohi, const __half* __restrict__ Olo,
        const __half* __restrict__ Wo,  const float* __restrict__ ob,
        const float* __restrict__ n1g,  const float* __restrict__ n1b,
        const __half* __restrict__ W1,  const float* __restrict__ f1b,
        const __half* __restrict__ W2,  const float* __restrict__ f2b,
        const float* __restrict__ n2g,  const float* __restrict__ n2b) {
    extern __shared__ __half smh[];
    __half* Hh  = smh;
    __half* Hl  = smh + 33792;
    __half* sOh = smh;
    __half* sOl = smh + 17408;
    __half* sWo = smh + 67584;
    __half* sW1 = smh + 67584;
    __half* sFh = smh + 67584;
    __half* sFl = smh + 76800;
    __half* sW2 = smh + 86016;

    const int tid = threadIdx.x, lane = tid & 31, warp = tid >> 5;
    const int row0 = blockIdx.x * 128;
    const int mwarp = warp >> 1, nwarp = warp & 1;
    const int fr = lane >> 2, fc = (lane & 3) * 2;
    const int ar = mwarp*16 + fr;

    // ---- stage O (SA=136) + Wo ----
    #pragma unroll 2
    for (int i = tid; i < 128*16; i += 512) {
        int r = i >> 4, c = (i & 15) * 8;
        size_t g = (size_t)(row0 + r)*128 + c;
        *reinterpret_cast<uint4*>(&sOh[r*136 + c]) = *reinterpret_cast<const uint4*>(&Ohi[g]);
        *reinterpret_cast<uint4*>(&sOl[r*136 + c]) = *reinterpret_cast<const uint4*>(&Olo[g]);
    }
    #pragma unroll 2
    for (int i = tid; i < 8192; i += 512) {
        int k = i >> 6, n4 = (i & 63) * 4;
        uint2 w2 = *reinterpret_cast<const uint2*>(&Wo[(size_t)k*Dd + n4]);
        __half tw[4]; *reinterpret_cast<uint2*>(tw) = w2;
        #pragma unroll
        for (int j = 0; j < 4; j++) sWo[(n4+j)*136 + k] = tw[j];
    }
    __syncthreads();

    // ---- ph0 MMA: v = O @ Wo (K=128) ----
    {
        float acc[16][4];
        #pragma unroll
        for (int i = 0; i < 16; i++)
            #pragma unroll
            for (int j = 0; j < 4; j++) acc[i][j] = 0.f;
        #pragma unroll
        for (int kk = 0; kk < 8; kk++) {
            uint32_t ah[4], al[4];
            const __half* pa = &sOh[ar*136 + kk*16 + fc];
            ah[0] = *(const uint32_t*)pa;
            ah[1] = *(const uint32_t*)(pa + 8*136);
            ah[2] = *(const uint32_t*)(pa + 8);
            ah[3] = *(const uint32_t*)(pa + 8*136 + 8);
            const __half* pl = &sOl[ar*136 + kk*16 + fc];
            al[0] = *(const uint32_t*)pl;
            al[1] = *(const uint32_t*)(pl + 8*136);
            al[2] = *(const uint32_t*)(pl + 8);
            al[3] = *(const uint32_t*)(pl + 8*136 + 8);
            #pragma unroll
            for (int nt = 0; nt < 16; nt++) {
                int nrow = nwarp*128 + nt*8 + fr;
                const __half* pb = &sWo[nrow*136 + kk*16 + fc];
                uint32_t b0 = *(const uint32_t*)pb;
                uint32_t b1 = *(const uint32_t*)(pb + 8);
                mma16816h(acc[nt], ah, b0, b1);
                mma16816h(acc[nt], al, b0, b1);
            }
        }
        __syncthreads();   // O tile + Wo dead

        // write v+bias pairs into H; stage W1 concurrently
        #pragma unroll
        for (int nt = 0; nt < 16; nt++) {
            int c = nwarp*128 + nt*8 + fc;
            float b0v = ob[c], b1v = ob[c+1];
            #pragma unroll
            for (int half = 0; half < 2; half++) {
                int r = mwarp*16 + fr + half*8;
                fsplit_h(acc[nt][half*2+0] + b0v, Hh[r*264 + c],     Hl[r*264 + c]);
                fsplit_h(acc[nt][half*2+1] + b1v, Hh[r*264 + c + 1], Hl[r*264 + c + 1]);
            }
        }
    }
    #pragma unroll 2
    for (int i = tid; i < 4096; i += 512) {
        int k = i >> 4, n4 = (i & 15) * 4;
        uint2 w2 = *reinterpret_cast<const uint2*>(&W1[(size_t)k*FCd + n4]);
        __half tw[4]; *reinterpret_cast<uint2*>(tw) = w2;
        #pragma unroll
        for (int j = 0; j < 4; j++) sW1[(n4+j)*264 + k] = tw[j];
    }
    __syncthreads();

    // ---- LN1: h1 = LN(h_prev + v), in place ----
    #pragma unroll 1
    for (int rr = 0; rr < 8; rr++) {
        int row = warp*8 + rr;
        int token = row0 + row;
        float x[8], s = 0.f;
        #pragma unroll
        for (int j = 0; j < 8; j++) {
            int cix = lane*8 + j;
            size_t gix = (size_t)token*Dd + cix;
            x[j] = __half2float(Hh[row*264 + cix]) + __half2float(Hl[row*264 + cix])
                 + __half2float(g_hh[gix]) + __half2float(g_hl[gix]);
            s += x[j];
        }
        #pragma unroll
        for (int o = 16; o; o >>= 1) s += __shfl_xor_sync(~0u, s, o);
        float mean = s * (1.f/256.f);
        float v = 0.f;
        #pragma unroll
        for (int j = 0; j < 8; j++) { float d = x[j] - mean; v += d*d; }
        #pragma unroll
        for (int o = 16; o; o >>= 1) v += __shfl_xor_sync(~0u, v, o);
        float rstd = rsqrtf(v * (1.f/256.f) + EPSLN);
        #pragma unroll
        for (int j = 0; j < 8; j++) {
            int cix = lane*8 + j;
            float y = (x[j] - mean)*rstd*n1g[cix] + n1b[cix];
            fsplit_h(y, Hh[row*264 + cix], Hl[row*264 + cix]);
        }
    }
    __syncthreads();

    // ---- ph1 MMA: f = relu(h1 @ W1 + f1b) (K=256, N=64) ----
    {
        float acc[4][4];
        #pragma unroll
        for (int i = 0; i < 4; i++)
            #pragma unroll
            for (int j = 0; j < 4; j++) acc[i][j] = 0.f;
        #pragma unroll
        for (int kk = 0; kk < 16; kk++) {
            uint32_t ah[4], al[4];
            const __half* pa = &Hh[ar*264 + kk*16 + fc];
            ah[0] = *(const uint32_t*)pa;
            ah[1] = *(const uint32_t*)(pa + 8*264);
            ah[2] = *(const uint32_t*)(pa + 8);
            ah[3] = *(const uint32_t*)(pa + 8*264 + 8);
            const __half* pl = &Hl[ar*264 + kk*16 + fc];
            al[0] = *(const uint32_t*)pl;
            al[1] = *(const uint32_t*)(pl + 8*264);
            al[2] = *(const uint32_t*)(pl + 8);
            al[3] = *(const uint32_t*)(pl + 8*264 + 8);
            #pragma unroll
            for (int nt = 0; nt < 4; nt++) {
                int nrow = nwarp*32 + nt*8 + fr;
                const __half* pb = &sW1[nrow*264 + kk*16 + fc];
                uint32_t b0 = *(const uint32_t*)pb;
                uint32_t b1 = *(const uint32_t*)(pb + 8);
                mma16816h(acc[nt], ah, b0, b1);
                mma16816h(acc[nt], al, b0, b1);
            }
        }
        __syncthreads();   // W1 dead (f region overlaps it)

        #pragma unroll
        for (int nt = 0; nt < 4; nt++) {
            int c = nwarp*32 + nt*8 + fc;
            float b0v = f1b[c], b1v = f1b[c+1];
            #pragma unroll
            for (int half = 0; half < 2; half++) {
                int r = mwarp*16 + fr + half*8;
                float v0 = fmaxf(acc[nt][half*2+0] + b0v, 0.f);
                float v1 = fmaxf(acc[nt][half*2+1] + b1v, 0.f);
                fsplit_h(v0, sFh[r*72 + c],     sFl[r*72 + c]);
                fsplit_h(v1, sFh[r*72 + c + 1], sFl[r*72 + c + 1]);
            }
        }
    }
    #pragma unroll 2
    for (int i = tid; i < 4096; i += 512) {
        int k = i >> 6, n4 = (i & 63) * 4;
        uint2 w2 = *reinterpret_cast<const uint2*>(&W2[(size_t)k*Dd + n4]);
        __half tw[4]; *reinterpret_cast<uint2*>(tw) = w2;
        #pragma unroll
        for (int j = 0; j < 4; j++) sW2[(n4+j)*72 + k] = tw[j];
    }
    __syncthreads();

    // ---- ph2 MMA: v2 = f @ W2 (K=64, N=256); x = h1 + v2 + f2b (RMW H) ----
    {
        float acc[16][4];
        #pragma unroll
        for (int i = 0; i < 16; i++)
            #pragma unroll
            for (int j = 0; j < 4; j++) acc[i][j] = 0.f;
        #pragma unroll
        for (int kk = 0; kk < 4; kk++) {
            uint32_t ah[4], al[4];
            const __half* pa = &sFh[ar*72 + kk*16 + fc];
            ah[0] = *(const uint32_t*)pa;
            ah[1] = *(const uint32_t*)(pa + 8*72);
            ah[2] = *(const uint32_t*)(pa + 8);
            ah[3] = *(const uint32_t*)(pa + 8*72 + 8);
            const __half* pl = &sFl[ar*72 + kk*16 + fc];
            al[0] = *(const uint32_t*)pl;
            al[1] = *(const uint32_t*)(pl + 8*72);
            al[2] = *(const uint32_t*)(pl + 8);
            al[3] = *(const uint32_t*)(pl + 8*72 + 8);
            #pragma unroll
            for (int nt = 0; nt < 16; nt++) {
                int nrow = nwarp*128 + nt*8 + fr;
                const __half* pb = &sW2[nrow*72 + kk*16 + fc];
                uint32_t b0 = *(const uint32_t*)pb;
                uint32_t b1 = *(const uint32_t*)(pb + 8);
                mma16816h(acc[nt], ah, b0, b1);
                mma16816h(acc[nt], al, b0, b1);
            }
        }
        // RMW H: x = h1 + v2 + bias (each (r,c) has a single owner thread)
        #pragma unroll
        for (int nt = 0; nt < 16; nt++) {
            int c = nwarp*128 + nt*8 + fc;
            float b0v = f2b[c], b1v = f2b[c+1];
            #pragma unroll
            for (int half = 0; half < 2; half++) {
                int r = mwarp*16 + fr + half*8;
                float h10 = __half2float(Hh[r*264 + c])   + __half2float(Hl[r*264 + c]);
                float h11 = __half2float(Hh[r*264 + c+1]) + __half2float(Hl[r*264 + c+1]);
                fsplit_h(h10 + acc[nt][half*2+0] + b0v, Hh[r*264 + c],   Hl[r*264 + c]);
                fsplit_h(h11 + acc[nt][half*2+1] + b1v, Hh[r*264 + c+1], Hl[r*264 + c+1]);
            }
        }
    }
    __syncthreads();

    // ---- LN2 -> global h ----
    #pragma unroll 1
    for (int rr = 0; rr < 8; rr++) {
        int row = warp*8 + rr;
        int token = row0 + row;
        float x[8], s = 0.f;
        #pragma unroll
        for (int j = 0; j < 8; j++) {
            int cix = lane*8 + j;
            x[j] = __half2float(Hh[row*264 + cix]) + __half2float(Hl[row*264 + cix]);
            s += x[j];
        }
        #pragma unroll
        for (int o = 16; o; o >>= 1) s += __shfl_xor_sync(~0u, s, o);
        float mean = s * (1.f/256.f);
        float v = 0.f;
        #pragma unroll
        for (int j = 0; j < 8; j++) { float d = x[j] - mean; v += d*d; }
        #pragma unroll
        for (int o = 16; o; o >>= 1) v += __shfl_xor_sync(~0u, v, o);
        float rstd = rsqrtf(v * (1.f/256.f) + EPSLN);
        #pragma unroll
        for (int j = 0; j < 8; j++) {
            int cix = lane*8 + j;
            float y = (x[j] - mean)*rstd*n2g[cix] + n2b[cix];
            size_t ix = (size_t)token*Dd + cix;
            fsplit_h(y, g_hh[ix], g_hl[ix]);
        }
    }
}

// ---------------------------------------------------------------------------
// Attention (fp16): 128-query tile, 256 threads (8 warps x 16 rows).
// Single-term fp16 MMA (Q pre-scaled by SCALE*log2e in QKV GEMM).
// Pass A: row sums (4-buffer K ring, 2 chunks/barrier). Pass B: QK (SW
// pipelined), P out (.cs), PV. smem 40KB -> 3 CTAs/SM.
// Zfilled padding keys -> score exactly 0 -> exp exactly 1 -> subtract 32.
// ---------------------------------------------------------------------------
#define QT 128
#define KT 128
#define NCH 16
#define NPAD 32.0f

#define BUFB 10240                 // bytes per 128x40-half buffer
#define SM_ATTN_BYTES (4*BUFB)     // 40960

__device__ __forceinline__ void stage1(uint32_t sm_u, int bufoff, int ch,
        const __half* P, size_t base, int tid) {
    const int k0 = ch * KT;
    #pragma unroll
    for (int it = 0; it < 2; it++) {
        int o = tid + it*256;
        int r = o >> 2;
        int c = (o & 3) * 8;
        int s = k0 + r;
        bool ok = s < Ld;
        const __half* src = P + base + (size_t)(ok ? s : 0)*128 + c;
        uint32_t dst = sm_u + bufoff + (r*40 + c)*2;
        cpa16(dst, src, ok ? 16 : 0);
    }
}

__device__ __forceinline__ void qk_stats_chunk(
        uint32_t kh_u, int laneK,
        const uint32_t aq[2][4],
        float& s0, float& s1) {
    #pragma unroll 2
    for (int gq = 0; gq < 4; gq++) {
        float acc[4][4];
        #pragma unroll
        for (int i = 0; i < 4; i++)
            #pragma unroll
            for (int j = 0; j < 4; j++) acc[i][j] = 0.f;
        #pragma unroll
        for (int pair = 0; pair < 2; pair++) {
            int be = (gq*32 + pair*16)*40;
            #pragma unroll
            for (int kk = 0; kk < 2; kk++) {
                uint32_t b0, b1, b2, b3;
                uint32_t off = (be + kk*16 + laneK)*2;
                ldsm4(b0, b1, b2, b3, kh_u + off);
                mma16816h(acc[pair*2  ], aq[kk], b0, b1);
                mma16816h(acc[pair*2+1], aq[kk], b2, b3);
            }
        }
        #pragma unroll
        for (int nt = 0; nt < 4; nt++) {
            s0 += ex2(acc[nt][0]) + ex2(acc[nt][1]);
            s1 += ex2(acc[nt][2]) + ex2(acc[nt][3]);
        }
    }
}

__device__ __forceinline__ void qk_group(
        uint32_t kh_u, int laneK, int kbe,
        const uint32_t aq[2][4], float acc[2][4]) {
    #pragma unroll
    for (int i = 0; i < 2; i++)
        #pragma unroll
        for (int j = 0; j < 4; j++) acc[i][j] = 0.f;
    #pragma unroll
    for (int kk = 0; kk < 2; kk++) {
        uint32_t b0, b1, b2, b3;
        uint32_t off = (kbe + kk*16 + laneK)*2;
        ldsm4(b0, b1, b2, b3, kh_u + off);
        mma16816h(acc[0], aq[kk], b0, b1);
        mma16816h(acc[1], aq[kk], b2, b3);
    }
}

template<bool MASK>
__device__ __forceinline__ void emit_group(
        uint32_t vh_u, int laneV, int g, int k0, int fc,
        float inv0, float inv1,
        float* prow0, float* prow1, bool wr0, bool wr1,
        const float acc[2][4], float oacc[4][4]) {
    int kbe = g*16*40;
    int colb = k0 + g*16 + fc;
    bool ok0 = !MASK || (colb < Ld);
    bool ok1 = !MASK || (colb + 8 < Ld);
    float p00 = ok0 ? ex2(acc[0][0])*inv0 : 0.f;
    float p01 = ok0 ? ex2(acc[0][1])*inv0 : 0.f;
    float p02 = ok0 ? ex2(acc[0][2])*inv1 : 0.f;
    float p03 = ok0 ? ex2(acc[0][3])*inv1 : 0.f;
    float p10 = ok1 ? ex2(acc[1][0])*inv0 : 0.f;
    float p11 = ok1 ? ex2(acc[1][1])*inv0 : 0.f;
    float p12 = ok1 ? ex2(acc[1][2])*inv1 : 0.f;
    float p13 = ok1 ? ex2(acc[1][3])*inv1 : 0.f;

    if (wr0) {
        if (ok0) stcs2(&prow0[colb],     p00, p01);
        if (ok1) stcs2(&prow0[colb + 8], p10, p11);
    }
    if (wr1) {
        if (ok0) stcs2(&prow1[colb],     p02, p03);
        if (ok1) stcs2(&prow1[colb + 8], p12, p13);
    }

    uint32_t ah[4];
    ah[0] = pk2h(p00, p01);
    ah[1] = pk2h(p02, p03);
    ah[2] = pk2h(p10, p11);
    ah[3] = pk2h(p12, p13);

    #pragma unroll
    for (int dp = 0; dp < 2; dp++) {
        uint32_t v0, v1, v2, v3;
        uint32_t off = (kbe + dp*16 + laneV)*2;
        ldsm4t(v0, v1, v2, v3, vh_u + off);
        mma16816h(oacc[dp*2  ], ah, v0, v1);
        mma16816h(oacc[dp*2+1], ah, v2, v3);
    }
}

template<bool MASK>
__device__ __forceinline__ void qk_emit_chunk(
        uint32_t kh_u, uint32_t vh_u, int laneK, int laneV,
        const uint32_t aq[2][4],
        int k0, int fc, float inv0, float inv1,
        float* prow0, float* prow1, bool wr0, bool wr1,
        float oacc[4][4]) {
    float aA[2][4], aB[2][4];
    qk_group(kh_u, laneK, 0, aq, aA);
    #pragma unroll
    for (int g = 0; g < 8; g += 2) {
        qk_group(kh_u, laneK, (g+1)*640, aq, aB);
        emit_group<MASK>(vh_u, laneV, g, k0, fc, inv0, inv1,
                         prow0, prow1, wr0, wr1, aA, oacc);
        if (g + 2 < 8)
            qk_group(kh_u, laneK, (g+2)*640, aq, aA);
        emit_group<MASK>(vh_u, laneV, g+1, k0, fc, inv0, inv1,
                         prow0, prow1, wr0, wr1, aB, oacc);
    }
}

__global__ __launch_bounds__(256, 3) void attn_kernel(
        const __half* __restrict__ qkv,
        float* __restrict__ Pout,
        __half* __restrict__ Oh, __half* __restrict__ Ol) {
    extern __shared__ __half smh[];
    uint32_t sm_u = (uint32_t)__cvta_generic_to_shared(smh);

    const int tid = threadIdx.x, lane = tid & 31, warp = tid >> 5;
    const int bh = blockIdx.y;
    const int b  = bh >> 2, h = bh & 3;
    const int q0 = blockIdx.x * QT;
    const size_t base = ((size_t)b*Ld*Hd + h)*DKd;
    const __half* Q = qkv;
    const __half* K = qkv + (size_t)BLd*128;
    const __half* V = qkv + (size_t)2*BLd*128;

    const int mrow = warp * 16;
    const int fr = lane >> 2, fc = (lane & 3) * 2;
    const int lr = lane & 7, sel = lane >> 3;
    const int laneK = ((sel>>1)*8 + lr)*40 + (sel&1)*8;
    const int laneV = ((sel&1)*8 + lr)*40 + (sel>>1)*8;

    const int r0g = q0 + mrow + fr, r1g = r0g + 8;
    const bool q0ok = (r0g < Ld), q1ok = (r1g < Ld);
    uint32_t aq[2][4];
    #pragma unroll
    for (int kk = 0; kk < 2; kk++) {
        int c = kk*16 + fc;
        size_t g0 = base + (size_t)r0g*128 + c;
        size_t g1 = base + (size_t)r1g*128 + c;
        aq[kk][0] = q0ok ? *(const uint32_t*)&Q[g0]     : 0;
        aq[kk][1] = q1ok ? *(const uint32_t*)&Q[g1]     : 0;
        aq[kk][2] = q0ok ? *(const uint32_t*)&Q[g0 + 8] : 0;
        aq[kk][3] = q1ok ? *(const uint32_t*)&Q[g1 + 8] : 0;
    }

    float s0 = 0.f, s1 = 0.f;

    // ======== PASS A: row sums (K only, 4-buffer ring, 2 chunks/sync) ====
    stage1(sm_u, 0*BUFB, 0, K, base, tid);
    stage1(sm_u, 1*BUFB, 1, K, base, tid); cpa_commit();
    stage1(sm_u, 2*BUFB, 2, K, base, tid);
    stage1(sm_u, 3*BUFB, 3, K, base, tid); cpa_commit();
    #pragma unroll 1
    for (int it = 0; it < 8; it++) {
        if (it < 7) cpa_wait<1>(); else cpa_wait<0>();
        __syncthreads();
        int b0 = (it & 1) ? 2 : 0;
        qk_stats_chunk(sm_u + b0*BUFB,     laneK, aq, s0, s1);
        qk_stats_chunk(sm_u + (b0+1)*BUFB, laneK, aq, s0, s1);
        __syncthreads();
        if (it < 6) {
            stage1(sm_u, b0*BUFB,     2*it+4, K, base, tid);
            stage1(sm_u, (b0+1)*BUFB, 2*it+5, K, base, tid);
            cpa_commit();
        }
    }

    // prologue for pass B overlaps the reduction: K in bufs 0/1, V in 2/3
    stage1(sm_u, 0*BUFB, 0, K, base, tid);
    stage1(sm_u, 2*BUFB, 0, V, base, tid); cpa_commit();
    stage1(sm_u, 1*BUFB, 1, K, base, tid);
    stage1(sm_u, 3*BUFB, 1, V, base, tid); cpa_commit();

    s0 += __shfl_xor_sync(~0u, s0, 1);
    s0 += __shfl_xor_sync(~0u, s0, 2);
    s1 += __shfl_xor_sync(~0u, s1, 1);
    s1 += __shfl_xor_sync(~0u, s1, 2);
    s0 -= NPAD;
    s1 -= NPAD;
    const float inv0 = 1.f / s0, inv1 = 1.f / s1;

    // ======== PASS B: P out + PV ========
    float oacc[4][4];
    #pragma unroll
    for (int i = 0; i < 4; i++)
        #pragma unroll
        for (int j = 0; j < 4; j++) oacc[i][j] = 0.f;

    float* prow0 = &Pout[((size_t)bh*Ld + r0g)*Ld];
    float* prow1 = prow0 + 8*(size_t)Ld;

    #pragma unroll 1
    for (int ch = 0; ch < NCH; ch++) {
        if (ch < NCH-1) cpa_wait<1>(); else cpa_wait<0>();
        __syncthreads();
        int buf = ch & 1;
        uint32_t kh_u = sm_u + buf*BUFB;
        uint32_t vh_u = sm_u + (2 + buf)*BUFB;
        if (ch < NCH-1)
            qk_emit_chunk<false>(kh_u, vh_u, laneK, laneV, aq,
                                 ch*KT, fc, inv0, inv1, prow0, prow1, q0ok, q1ok, oacc);
        else
            qk_emit_chunk<true >(kh_u, vh_u, laneK, laneV, aq,
                                 ch*KT, fc, inv0, inv1, prow0, prow1, q0ok, q1ok, oacc);
        __syncthreads();
        if (ch + 2 < NCH) {
            stage1(sm_u, buf*BUFB,       ch+2, K, base, tid);
            stage1(sm_u, (2 + buf)*BUFB, ch+2, V, base, tid);
            cpa_commit();
        }
    }

    // ---- write O (split fp16) ----
    #pragma unroll
    for (int dt = 0; dt < 4; dt++) {
        int d = dt*8 + fc;
        if (q0ok) {
            size_t g = base + (size_t)r0g*128 + d;
            __half hh, ll;
            fsplit_h(oacc[dt][0], hh, ll); Oh[g]   = hh; Ol[g]   = ll;
            fsplit_h(oacc[dt][1], hh, ll); Oh[g+1] = hh; Ol[g+1] = ll;
        }
        if (q1ok) {
            size_t g = base + (size_t)r1g*128 + d;
            __half hh, ll;
            fsplit_h(oacc[dt][2], hh, ll); Oh[g]   = hh; Ol[g]   = ll;
            fsplit_h(oacc[dt][3], hh, ll); Oh[g+1] = hh; Ol[g+1] = ll;
        }
    }
}

// ---------------------------------------------------------------------------
// Final head tail: out = relu_h(g_tmp fp32) @ o2w + o2b   (warp per token)
// ---------------------------------------------------------------------------
__global__ __launch_bounds__(256) void head2_kernel(const float* __restrict__ o2w,
                                                    const float* __restrict__ o2b,
                                                    float* __restrict__ out) {
    int warp = threadIdx.x >> 5, lane = threadIdx.x & 31;
    int token = blockIdx.x * 8 + warp;
    const float* hp = &g_tmp[(size_t)token*Dd];
    float a0 = 0.f, a1 = 0.f;
    #pragma unroll
    for (int j = 0; j < 8; j++) {
        int k = lane + j*32;
        float hv = hp[k];
        a0 = fmaf(hv, o2w[k*2],   a0);
        a1 = fmaf(hv, o2w[k*2+1], a1);
    }
    #pragma unroll
    for (int o = 16; o; o >>= 1) {
        a0 += __shfl_xor_sync(~0u, a0, o);
        a1 += __shfl_xor_sync(~0u, a1, o);
    }
    if (lane == 0) {
        out[(size_t)token*2]     = a0 + o2b[0];
        out[(size_t)token*2 + 1] = a1 + o2b[1];
    }
}

// ---------------------------------------------------------------------------
// Host orchestration
// ---------------------------------------------------------------------------
static inline void* symaddr(const void* s) {
    void* p = nullptr;
    cudaGetSymbolAddress(&p, s);
    return p;
}

extern "C" void kernel_launch(void* const* d_in, const int* in_sizes, int n_in,
                              void* d_out, int out_size) {
    const float* x    = (const float*)d_in[0];
    const float* in_w = (const float*)d_in[1];
    const float* in_b = (const float*)d_in[2];
    const float* qw   = (const float*)d_in[3];
    const float* qb   = (const float*)d_in[4];
    const float* kw   = (const float*)d_in[5];
    const float* kb   = (const float*)d_in[6];
    const float* vw   = (const float*)d_in[7];
    const float* vb   = (const float*)d_in[8];
    const float* ow   = (const float*)d_in[9];
    const float* ob   = (const float*)d_in[10];
    const float* f1w  = (const float*)d_in[11];
    const float* f1b  = (const float*)d_in[12];
    const float* f2w  = (const float*)d_in[13];
    const float* f2b  = (const float*)d_in[14];
    const float* n1g  = (const float*)d_in[15];
    const float* n1b  = (const float*)d_in[16];
    const float* n2g  = (const float*)d_in[17];
    const float* n2b  = (const float*)d_in[18];
    const float* o1w  = (const float*)d_in[19];
    const float* o1b  = (const float*)d_in[20];
    const float* o2w  = (const float*)d_in[21];
    const float* o2b  = (const float*)d_in[22];

    float* outp     = (float*)d_out;
    float* attn_out = outp + (size_t)Bd*Ld*2;

    __half* p_hh   = (__half*)symaddr(g_hh);
    __half* p_hl   = (__half*)symaddr(g_hl);
    __half* p_qkv  = (__half*)symaddr(g_qkv);
    __half* p_oh   = (__half*)symaddr(g_oh);
    __half* p_ol   = (__half*)symaddr(g_ol);
    float*  p_tmp  = (float*)symaddr(g_tmp);
    __half* p_ow   = (__half*)symaddr(g_ow);
    __half* p_f1w  = (__half*)symaddr(g_f1w);
    __half* p_f2w  = (__half*)symaddr(g_f2w);
    __half* p_o1w  = (__half*)symaddr(g_o1w);

    const int SM_G256 = (2*128*(256+8) + 64*(256+8))*2;      // 168960

    cudaFuncSetAttribute(gemm_qkv, cudaFuncAttributeMaxDynamicSharedMemorySize, SM_G256);
    cudaFuncSetAttribute(gemm_bias<256,0,true>, cudaFuncAttributeMaxDynamicSharedMemorySize, SM_G256);
    cudaFuncSetAttribute(fused_tail, cudaFuncAttributeMaxDynamicSharedMemorySize, SM_TAIL_BYTES);
    cudaFuncSetAttribute(attn_kernel, cudaFuncAttributeMaxDynamicSharedMemorySize, SM_ATTN_BYTES);

    convert_w<<<384, 256>>>(qw, kw, vw, ow, f1w, f2w, o1w, qb, kb, vb);
    embed_kernel<<<BLd, Dd>>>(x, in_w, in_b);

    const dim3 gQKV (BLd/128, 6);
    const dim3 gProj(BLd/128, 4);   // N=256 (head only)
    const dim3 gLN  (BLd/128);
    const dim3 gAttn((Ld + QT - 1)/QT, Bd*Hd);

    for (int i = 0; i < NLd; i++) {
        gemm_qkv<<<gQKV, 512, SM_G256>>>(i);

        attn_kernel<<<gAttn, 256, SM_ATTN_BYTES>>>(
            p_qkv, attn_out + (size_t)i*Bd*Hd*Ld*Ld, p_oh, p_ol);

        fused_tail<<<gLN, 512, SM_TAIL_BYTES>>>(
            p_oh, p_ol,
            p_ow + (size_t)i*128*Dd, ob + i*Dd,
            n1g + i*Dd, n1b + i*Dd,
            p_f1w + (size_t)i*Dd*FCd, f1b + i*FCd,
            p_f2w + (size_t)i*FCd*Dd, f2b + i*Dd,
            n2g + i*Dd, n2b + i*Dd);
    }

    gemm_bias<256,0,true><<<gProj, 512, SM_G256>>>(
        p_hh, p_hl, p_o1w, o1b, p_tmp, nullptr, Dd);
    head2_kernel<<<BLd/8, 256>>>(o2w, o2b, outp);
}

// round 17
// speedup vs baseline: 1.5963x; 1.0650x over previous
#include <cuda_runtime.h>
#include <cuda_bf16.h>
#include <cuda_fp16.h>
#include <stdint.h>

#define Bd  8
#define Ld  2016
#define Hd  4
#define DKd 32
#define Dd  256
#define FCd 64
#define NLd 3
#define BLd (Bd*Ld)          // 16128 tokens

#define SC2f 0.09016844005556f   // (1/sqrt(256)) * log2(e)
#define EPSLN 1e-5f

// ---------------------------------------------------------------------------
// Device scratch. Residual stream: split fp16 only. Weights: fp16.
// ---------------------------------------------------------------------------
__device__ __align__(128) __half  g_hh   [BLd*Dd];
__device__ __align__(128) __half  g_hl   [BLd*Dd];
__device__ __align__(128) __half  g_qkv  [3*BLd*128];   // fp16 (Q pre-scaled)
__device__ __align__(128) __half  g_oh   [BLd*128];
__device__ __align__(128) __half  g_ol   [BLd*128];
__device__ __align__(128) float   g_tmp  [BLd*Dd];
// fp16 weights
__device__ __align__(128) __half  g_qkvw [NLd*3*Dd*128];
__device__ __align__(128) float   g_qkvb [NLd*3*128];
__device__ __align__(128) __half  g_ow   [NLd*128*Dd];
__device__ __align__(128) __half  g_f1w  [NLd*Dd*FCd];
__device__ __align__(128) __half  g_f2w  [NLd*FCd*Dd];
__device__ __align__(128) __half  g_o1w  [Dd*Dd];

// ---------------------------------------------------------------------------
// helpers
// ---------------------------------------------------------------------------
__device__ __forceinline__ void mma16816h(float* d, const uint32_t* a,
                                          uint32_t b0, uint32_t b1) {
    asm volatile(
        "mma.sync.aligned.m16n8k16.row.col.f32.f16.f16.f32 "
        "{%0,%1,%2,%3}, {%4,%5,%6,%7}, {%8,%9}, {%0,%1,%2,%3};"
        : "+f"(d[0]), "+f"(d[1]), "+f"(d[2]), "+f"(d[3])
        : "r"(a[0]), "r"(a[1]), "r"(a[2]), "r"(a[3]), "r"(b0), "r"(b1));
}

__device__ __forceinline__ void ldsm4(uint32_t& r0, uint32_t& r1,
                                      uint32_t& r2, uint32_t& r3, uint32_t a) {
    asm volatile("ldmatrix.sync.aligned.m8n8.x4.shared.b16 {%0,%1,%2,%3}, [%4];"
        : "=r"(r0), "=r"(r1), "=r"(r2), "=r"(r3) : "r"(a));
}

__device__ __forceinline__ void ldsm4t(uint32_t& r0, uint32_t& r1,
                                       uint32_t& r2, uint32_t& r3, uint32_t a) {
    asm volatile("ldmatrix.sync.aligned.m8n8.x4.trans.shared.b16 {%0,%1,%2,%3}, [%4];"
        : "=r"(r0), "=r"(r1), "=r"(r2), "=r"(r3) : "r"(a));
}

__device__ __forceinline__ void cpa16(uint32_t dst, const void* src, int srcsize) {
    asm volatile("cp.async.cg.shared.global [%0], [%1], 16, %2;"
        :: "r"(dst), "l"(src), "r"(srcsize));
}
__device__ __forceinline__ void cpa_commit() {
    asm volatile("cp.async.commit_group;" ::: "memory");
}
template<int N>
__device__ __forceinline__ void cpa_wait() {
    asm volatile("cp.async.wait_group %0;" :: "n"(N) : "memory");
}

__device__ __forceinline__ float ex2(float x) {
    float y;
    asm("ex2.approx.ftz.f32 %0, %1;" : "=f"(y) : "f"(x));
    return y;
}

__device__ __forceinline__ uint32_t pk2h(float x, float y) {
    __half2 t = __floats2half2_rn(x, y);
    return *reinterpret_cast<uint32_t*>(&t);
}

__device__ __forceinline__ void fsplit_h(float v, __half& hi, __half& lo) {
    hi = __float2half_rn(v);
    lo = __float2half_rn(v - __half2float(hi));
}

__device__ __forceinline__ void stcs4(float* p, float a, float b, float c, float d) {
    asm volatile("st.global.cs.v4.f32 [%0], {%1,%2,%3,%4};"
        :: "l"(p), "f"(a), "f"(b), "f"(c), "f"(d));
}

// ---------------------------------------------------------------------------
// Weight conversion fp32 -> fp16 (+ QKV packing)
// ---------------------------------------------------------------------------
__global__ void convert_w(const float* __restrict__ qw, const float* __restrict__ kw,
                          const float* __restrict__ vw, const float* __restrict__ ow,
                          const float* __restrict__ f1w, const float* __restrict__ f2w,
                          const float* __restrict__ o1w,
                          const float* __restrict__ qb, const float* __restrict__ kb,
                          const float* __restrict__ vb) {
    int i = blockIdx.x * 256 + threadIdx.x;
    const int n1 = NLd*Dd*128;
    const int n3 = NLd*Dd*FCd;
    const int n5 = Dd*Dd;
    if (i < n1) {
        int l = i / (Dd*128), rem = i % (Dd*128);
        size_t b = (size_t)(l*3)*Dd*128 + rem;
        g_qkvw[b]            = __float2half_rn(qw[i]);
        g_qkvw[b + Dd*128]   = __float2half_rn(kw[i]);
        g_qkvw[b + 2*Dd*128] = __float2half_rn(vw[i]);
        g_ow[i]              = __float2half_rn(ow[i]);
    }
    if (i < n3) {
        g_f1w[i] = __float2half_rn(f1w[i]);
        g_f2w[i] = __float2half_rn(f2w[i]);
    }
    if (i < n5) g_o1w[i] = __float2half_rn(o1w[i]);
    if (i < NLd*128) {
        int l = i >> 7, n = i & 127;
        g_qkvb[(l*3+0)*128 + n] = qb[i];
        g_qkvb[(l*3+1)*128 + n] = kb[i];
        g_qkvb[(l*3+2)*128 + n] = vb[i];
    }
}

// ---------------------------------------------------------------------------
// Embed: h = x @ in_w + in_b (split fp16)
// ---------------------------------------------------------------------------
__global__ void embed_kernel(const float* __restrict__ x,
                             const float* __restrict__ in_w,
                             const float* __restrict__ in_b) {
    int t = blockIdx.x, d = threadIdx.x;
    float x0 = x[t*2], x1 = x[t*2+1];
    float v = fmaf(x0, in_w[d], fmaf(x1, in_w[Dd + d], in_b[d]));
    size_t ix = (size_t)t*Dd + d;
    fsplit_h(v, g_hh[ix], g_hl[ix]);
}

// ---------------------------------------------------------------------------
// GEMM core: tile 128 x (NT*16), 512 threads (16 warps = 8M x 2N).
// 2-term split fp16 MMA (A = hi+lo fp16, W = single fp16).
// OM: 0=fp32, 2=fp16*scale.
// ---------------------------------------------------------------------------
template<int K, int NT, int OM, bool RELU>
__device__ __forceinline__ void gemm_body(
        const __half* __restrict__ Ahi,
        const __half* __restrict__ Alo,
        const __half* __restrict__ W,
        const float* __restrict__ bias,
        float* __restrict__ outF,
        __half* __restrict__ outH1, float oscale,
        int N, int row0, int col0) {
    extern __shared__ __half smh[];
    constexpr int SA = K + 8;
    constexpr int NC = NT * 16;          // columns per CTA
    __half* sAh = smh;
    __half* sAl = smh + 128 * SA;
    __half* sW  = smh + 256 * SA;

    const int tid = threadIdx.x, lane = tid & 31, warp = tid >> 5;

    constexpr int AV = K / 8;
    #pragma unroll 2
    for (int i = tid; i < 128 * AV; i += 512) {
        int r = i / AV, c = (i % AV) * 8;
        size_t g = (size_t)(row0 + r)*K + c;
        *reinterpret_cast<uint4*>(&sAh[r*SA + c]) = *reinterpret_cast<const uint4*>(&Ahi[g]);
        *reinterpret_cast<uint4*>(&sAl[r*SA + c]) = *reinterpret_cast<const uint4*>(&Alo[g]);
    }
    #pragma unroll 2
    for (int i = tid; i < NC * K / 4; i += 512) {
        int k = i / (NC/4), n4 = (i % (NC/4)) * 4;
        size_t g = (size_t)k*N + col0 + n4;
        uint2 w2 = *reinterpret_cast<const uint2*>(&W[g]);
        __half tw[4]; *reinterpret_cast<uint2*>(tw) = w2;
        #pragma unroll
        for (int j = 0; j < 4; j++) sW[(n4+j)*SA + k] = tw[j];
    }
    __syncthreads();

    float acc[NT][4];
    #pragma unroll
    for (int i = 0; i < NT; i++)
        #pragma unroll
        for (int j = 0; j < 4; j++) acc[i][j] = 0.f;

    const int mwarp = warp >> 1, nwarp = warp & 1;
    const int ar = mwarp*16 + (lane >> 2);
    const int ac = (lane & 3) * 2;
    #pragma unroll
    for (int kk = 0; kk < K/16; kk++) {
        uint32_t ah[4], al[4];
        {
            const __half* pa = &sAh[ar*SA + kk*16 + ac];
            ah[0] = *(const uint32_t*)pa;
            ah[1] = *(const uint32_t*)(pa + 8*SA);
            ah[2] = *(const uint32_t*)(pa + 8);
            ah[3] = *(const uint32_t*)(pa + 8*SA + 8);
            const __half* pl = &sAl[ar*SA + kk*16 + ac];
            al[0] = *(const uint32_t*)pl;
            al[1] = *(const uint32_t*)(pl + 8*SA);
            al[2] = *(const uint32_t*)(pl + 8);
            al[3] = *(const uint32_t*)(pl + 8*SA + 8);
        }
        #pragma unroll
        for (int nt = 0; nt < NT; nt++) {
            int nrow = nwarp*(NT*8) + nt*8 + (lane>>2);
            const __half* pb = &sW[nrow*SA + kk*16 + ac];
            uint32_t b0 = *(const uint32_t*)pb;
            uint32_t b1 = *(const uint32_t*)(pb + 8);
            mma16816h(acc[nt], ah, b0, b1);
            mma16816h(acc[nt], al, b0, b1);
        }
    }

    const int orow = row0 + mwarp*16 + (lane >> 2);
    #pragma unroll
    for (int nt = 0; nt < NT; nt++) {
        int c = col0 + nwarp*(NT*8) + nt*8 + (lane & 3)*2;
        float b0v = bias[c], b1v = bias[c+1];
        #pragma unroll
        for (int half = 0; half < 2; half++) {
            int r = orow + half*8;
            float v0 = acc[nt][half*2+0] + b0v;
            float v1 = acc[nt][half*2+1] + b1v;
            if (RELU) { v0 = fmaxf(v0, 0.f); v1 = fmaxf(v1, 0.f); }
            size_t o = (size_t)r*N + c;
            if (OM == 0) { outF[o] = v0; outF[o+1] = v1; }
            if (OM == 2) {
                __half2 t = __floats2half2_rn(v0*oscale, v1*oscale);
                *reinterpret_cast<__half2*>(&outH1[o]) = t;
            }
        }
    }
}

template<int K, int NT, int OM, bool RELU>
__global__ __launch_bounds__(512) void gemm_bias(
        const __half* __restrict__ Ahi, const __half* __restrict__ Alo,
        const __half* __restrict__ W,
        const float* __restrict__ bias,
        float* __restrict__ outF, __half* __restrict__ outH1,
        int N) {
    gemm_body<K, NT, OM, RELU>(Ahi, Alo, W, bias, outF, outH1, 1.f,
                               N, blockIdx.x*128, blockIdx.y*(NT*16));
}

// Fused QKV: grid (126, 3); each CTA computes the full 128 cols of one of
// q/k/v. Writes fp16 (Q pre-scaled by SCALE*log2e).
__global__ __launch_bounds__(512) void gemm_qkv(int layer) {
    int sel = blockIdx.y;
    const __half* W = g_qkvw + ((size_t)(layer*3 + sel))*Dd*128;
    const float* bias = g_qkvb + (layer*3 + sel)*128;
    __half* oh = g_qkv + (size_t)sel*BLd*128;
    float oscale = (sel == 0) ? SC2f : 1.f;
    gemm_body<256, 8, 2, false>(g_hh, g_hl, W, bias, nullptr, oh, oscale,
                                128, blockIdx.x*128, 0);
}

// ---------------------------------------------------------------------------
// Fused layer tail (unchanged from R16): o-proj+LN1 -> FFN1 -> FFN2+LN2,
// all in smem per 128 rows.
// ---------------------------------------------------------------------------
#define SM_TAIL_BYTES 208896

__global__ __launch_bounds__(512, 1) void fused_tail(
        const __half* __restrict__ Ohi, const __half* __restrict__ Olo,
        const __half* __restrict__ Wo,  const float* __restrict__ ob,
        const float* __restrict__ n1g,  const float* __restrict__ n1b,
        const __half* __restrict__ W1,  const float* __restrict__ f1b,
        const __half* __restrict__ W2,  const float* __restrict__ f2b,
        const float* __restrict__ n2g,  const float* __restrict__ n2b) {
    extern __shared__ __half smh[];
    __half* Hh  = smh;
    __half* Hl  = smh + 33792;
    __half* sOh = smh;
    __half* sOl = smh + 17408;
    __half* sWo = smh + 67584;
    __half* sW1 = smh + 67584;
    __half* sFh = smh + 67584;
    __half* sFl = smh + 76800;
    __half* sW2 = smh + 86016;

    const int tid = threadIdx.x, lane = tid & 31, warp = tid >> 5;
    const int row0 = blockIdx.x * 128;
    const int mwarp = warp >> 1, nwarp = warp & 1;
    const int fr = lane >> 2, fc = (lane & 3) * 2;
    const int ar = mwarp*16 + fr;

    #pragma unroll 2
    for (int i = tid; i < 128*16; i += 512) {
        int r = i >> 4, c = (i & 15) * 8;
        size_t g = (size_t)(row0 + r)*128 + c;
        *reinterpret_cast<uint4*>(&sOh[r*136 + c]) = *reinterpret_cast<const uint4*>(&Ohi[g]);
        *reinterpret_cast<uint4*>(&sOl[r*136 + c]) = *reinterpret_cast<const uint4*>(&Olo[g]);
    }
    #pragma unroll 2
    for (int i = tid; i < 8192; i += 512) {
        int k = i >> 6, n4 = (i & 63) * 4;
        uint2 w2 = *reinterpret_cast<const uint2*>(&Wo[(size_t)k*Dd + n4]);
        __half tw[4]; *reinterpret_cast<uint2*>(tw) = w2;
        #pragma unroll
        for (int j = 0; j < 4; j++) sWo[(n4+j)*136 + k] = tw[j];
    }
    __syncthreads();

    {
        float acc[16][4];
        #pragma unroll
        for (int i = 0; i < 16; i++)
            #pragma unroll
            for (int j = 0; j < 4; j++) acc[i][j] = 0.f;
        #pragma unroll
        for (int kk = 0; kk < 8; kk++) {
            uint32_t ah[4], al[4];
            const __half* pa = &sOh[ar*136 + kk*16 + fc];
            ah[0] = *(const uint32_t*)pa;
            ah[1] = *(const uint32_t*)(pa + 8*136);
            ah[2] = *(const uint32_t*)(pa + 8);
            ah[3] = *(const uint32_t*)(pa + 8*136 + 8);
            const __half* pl = &sOl[ar*136 + kk*16 + fc];
            al[0] = *(const uint32_t*)pl;
            al[1] = *(const uint32_t*)(pl + 8*136);
            al[2] = *(const uint32_t*)(pl + 8);
            al[3] = *(const uint32_t*)(pl + 8*136 + 8);
            #pragma unroll
            for (int nt = 0; nt < 16; nt++) {
                int nrow = nwarp*128 + nt*8 + fr;
                const __half* pb = &sWo[nrow*136 + kk*16 + fc];
                uint32_t b0 = *(const uint32_t*)pb;
                uint32_t b1 = *(const uint32_t*)(pb + 8);
                mma16816h(acc[nt], ah, b0, b1);
                mma16816h(acc[nt], al, b0, b1);
            }
        }
        __syncthreads();

        #pragma unroll
        for (int nt = 0; nt < 16; nt++) {
            int c = nwarp*128 + nt*8 + fc;
            float b0v = ob[c], b1v = ob[c+1];
            #pragma unroll
            for (int half = 0; half < 2; half++) {
                int r = mwarp*16 + fr + half*8;
                fsplit_h(acc[nt][half*2+0] + b0v, Hh[r*264 + c],     Hl[r*264 + c]);
                fsplit_h(acc[nt][half*2+1] + b1v, Hh[r*264 + c + 1], Hl[r*264 + c + 1]);
            }
        }
    }
    #pragma unroll 2
    for (int i = tid; i < 4096; i += 512) {
        int k = i >> 4, n4 = (i & 15) * 4;
        uint2 w2 = *reinterpret_cast<const uint2*>(&W1[(size_t)k*FCd + n4]);
        __half tw[4]; *reinterpret_cast<uint2*>(tw) = w2;
        #pragma unroll
        for (int j = 0; j < 4; j++) sW1[(n4+j)*264 + k] = tw[j];
    }
    __syncthreads();

    #pragma unroll 1
    for (int rr = 0; rr < 8; rr++) {
        int row = warp*8 + rr;
        int token = row0 + row;
        float x[8], s = 0.f;
        #pragma unroll
        for (int j = 0; j < 8; j++) {
            int cix = lane*8 + j;
            size_t gix = (size_t)token*Dd + cix;
            x[j] = __half2float(Hh[row*264 + cix]) + __half2float(Hl[row*264 + cix])
                 + __half2float(g_hh[gix]) + __half2float(g_hl[gix]);
            s += x[j];
        }
        #pragma unroll
        for (int o = 16; o; o >>= 1) s += __shfl_xor_sync(~0u, s, o);
        float mean = s * (1.f/256.f);
        float v = 0.f;
        #pragma unroll
        for (int j = 0; j < 8; j++) { float d = x[j] - mean; v += d*d; }
        #pragma unroll
        for (int o = 16; o; o >>= 1) v += __shfl_xor_sync(~0u, v, o);
        float rstd = rsqrtf(v * (1.f/256.f) + EPSLN);
        #pragma unroll
        for (int j = 0; j < 8; j++) {
            int cix = lane*8 + j;
            float y = (x[j] - mean)*rstd*n1g[cix] + n1b[cix];
            fsplit_h(y, Hh[row*264 + cix], Hl[row*264 + cix]);
        }
    }
    __syncthreads();

    {
        float acc[4][4];
        #pragma unroll
        for (int i = 0; i < 4; i++)
            #pragma unroll
            for (int j = 0; j < 4; j++) acc[i][j] = 0.f;
        #pragma unroll
        for (int kk = 0; kk < 16; kk++) {
            uint32_t ah[4], al[4];
            const __half* pa = &Hh[ar*264 + kk*16 + fc];
            ah[0] = *(const uint32_t*)pa;
            ah[1] = *(const uint32_t*)(pa + 8*264);
            ah[2] = *(const uint32_t*)(pa + 8);
            ah[3] = *(const uint32_t*)(pa + 8*264 + 8);
            const __half* pl = &Hl[ar*264 + kk*16 + fc];
            al[0] = *(const uint32_t*)pl;
            al[1] = *(const uint32_t*)(pl + 8*264);
            al[2] = *(const uint32_t*)(pl + 8);
            al[3] = *(const uint32_t*)(pl + 8*264 + 8);
            #pragma unroll
            for (int nt = 0; nt < 4; nt++) {
                int nrow = nwarp*32 + nt*8 + fr;
                const __half* pb = &sW1[nrow*264 + kk*16 + fc];
                uint32_t b0 = *(const uint32_t*)pb;
                uint32_t b1 = *(const uint32_t*)(pb + 8);
                mma16816h(acc[nt], ah, b0, b1);
                mma16816h(acc[nt], al, b0, b1);
            }
        }
        __syncthreads();

        #pragma unroll
        for (int nt = 0; nt < 4; nt++) {
            int c = nwarp*32 + nt*8 + fc;
            float b0v = f1b[c], b1v = f1b[c+1];
            #pragma unroll
            for (int half = 0; half < 2; half++) {
                int r = mwarp*16 + fr + half*8;
                float v0 = fmaxf(acc[nt][half*2+0] + b0v, 0.f);
                float v1 = fmaxf(acc[nt][half*2+1] + b1v, 0.f);
                fsplit_h(v0, sFh[r*72 + c],     sFl[r*72 + c]);
                fsplit_h(v1, sFh[r*72 + c + 1], sFl[r*72 + c + 1]);
            }
        }
    }
    #pragma unroll 2
    for (int i = tid; i < 4096; i += 512) {
        int k = i >> 6, n4 = (i & 63) * 4;
        uint2 w2 = *reinterpret_cast<const uint2*>(&W2[(size_t)k*Dd + n4]);
        __half tw[4]; *reinterpret_cast<uint2*>(tw) = w2;
        #pragma unroll
        for (int j = 0; j < 4; j++) sW2[(n4+j)*72 + k] = tw[j];
    }
    __syncthreads();

    {
        float acc[16][4];
        #pragma unroll
        for (int i = 0; i < 16; i++)
            #pragma unroll
            for (int j = 0; j < 4; j++) acc[i][j] = 0.f;
        #pragma unroll
        for (int kk = 0; kk < 4; kk++) {
            uint32_t ah[4], al[4];
            const __half* pa = &sFh[ar*72 + kk*16 + fc];
            ah[0] = *(const uint32_t*)pa;
            ah[1] = *(const uint32_t*)(pa + 8*72);
            ah[2] = *(const uint32_t*)(pa + 8);
            ah[3] = *(const uint32_t*)(pa + 8*72 + 8);
            const __half* pl = &sFl[ar*72 + kk*16 + fc];
            al[0] = *(const uint32_t*)pl;
            al[1] = *(const uint32_t*)(pl + 8*72);
            al[2] = *(const uint32_t*)(pl + 8);
            al[3] = *(const uint32_t*)(pl + 8*72 + 8);
            #pragma unroll
            for (int nt = 0; nt < 16; nt++) {
                int nrow = nwarp*128 + nt*8 + fr;
                const __half* pb = &sW2[nrow*72 + kk*16 + fc];
                uint32_t b0 = *(const uint32_t*)pb;
                uint32_t b1 = *(const uint32_t*)(pb + 8);
                mma16816h(acc[nt], ah, b0, b1);
                mma16816h(acc[nt], al, b0, b1);
            }
        }
        #pragma unroll
        for (int nt = 0; nt < 16; nt++) {
            int c = nwarp*128 + nt*8 + fc;
            float b0v = f2b[c], b1v = f2b[c+1];
            #pragma unroll
            for (int half = 0; half < 2; half++) {
                int r = mwarp*16 + fr + half*8;
                float h10 = __half2float(Hh[r*264 + c])   + __half2float(Hl[r*264 + c]);
                float h11 = __half2float(Hh[r*264 + c+1]) + __half2float(Hl[r*264 + c+1]);
                fsplit_h(h10 + acc[nt][half*2+0] + b0v, Hh[r*264 + c],   Hl[r*264 + c]);
                fsplit_h(h11 + acc[nt][half*2+1] + b1v, Hh[r*264 + c+1], Hl[r*264 + c+1]);
            }
        }
    }
    __syncthreads();

    #pragma unroll 1
    for (int rr = 0; rr < 8; rr++) {
        int row = warp*8 + rr;
        int token = row0 + row;
        float x[8], s = 0.f;
        #pragma unroll
        for (int j = 0; j < 8; j++) {
            int cix = lane*8 + j;
            x[j] = __half2float(Hh[row*264 + cix]) + __half2float(Hl[row*264 + cix]);
            s += x[j];
        }
        #pragma unroll
        for (int o = 16; o; o >>= 1) s += __shfl_xor_sync(~0u, s, o);
        float mean = s * (1.f/256.f);
        float v = 0.f;
        #pragma unroll
        for (int j = 0; j < 8; j++) { float d = x[j] - mean; v += d*d; }
        #pragma unroll
        for (int o = 16; o; o >>= 1) v += __shfl_xor_sync(~0u, v, o);
        float rstd = rsqrtf(v * (1.f/256.f) + EPSLN);
        #pragma unroll
        for (int j = 0; j < 8; j++) {
            int cix = lane*8 + j;
            float y = (x[j] - mean)*rstd*n2g[cix] + n2b[cix];
            size_t ix = (size_t)token*Dd + cix;
            fsplit_h(y, g_hh[ix], g_hl[ix]);
        }
    }
}

// ---------------------------------------------------------------------------
// Attention (fp16): 128-query tile, 256 threads (8 warps x 16 rows).
// Keys PERMUTED within each 16-key block when staged (sigma: slot j ->
// global col (j&1) + ((j>>3)&1)*2 + (j&6)*2) for BOTH K and V, so each
// thread's 4 P values are 4 consecutive global columns -> one st.v4 per row.
// QK^T / row-sums / PV are contraction-order invariant. Masking is whole-
// group (Ld = 126*16). Zfilled pad keys -> exp exactly 1 -> subtract 32.
// ---------------------------------------------------------------------------
#define QT 128
#define KT 128
#define NCH 16
#define NPAD 32.0f

#define BUFB 10240                 // bytes per 128x40-half buffer
#define SM_ATTN_BYTES (4*BUFB)     // 40960

__device__ __forceinline__ void stage1(uint32_t sm_u, int bufoff, int ch,
        const __half* P, size_t base, int tid) {
    const int k0 = ch * KT;
    #pragma unroll
    for (int it = 0; it < 2; it++) {
        int o = tid + it*256;
        int r = o >> 2;                         // global key row within chunk
        int c = (o & 3) * 8;
        int s = k0 + r;
        bool ok = s < Ld;
        // permuted smem slot: slot sigma^-1(r mod 16) within the 16-block
        int m = r & 15;
        int slot = (r & ~15) | ((m & 1) | ((m & 2) << 2) | ((m >> 1) & 6));
        const __half* src = P + base + (size_t)(ok ? s : 0)*128 + c;
        uint32_t dst = sm_u + bufoff + (slot*40 + c)*2;
        cpa16(dst, src, ok ? 16 : 0);
    }
}

__device__ __forceinline__ void qk_stats_chunk(
        uint32_t kh_u, int laneK,
        const uint32_t aq[2][4],
        float& s0, float& s1) {
    #pragma unroll 2
    for (int gq = 0; gq < 4; gq++) {
        float acc[4][4];
        #pragma unroll
        for (int i = 0; i < 4; i++)
            #pragma unroll
            for (int j = 0; j < 4; j++) acc[i][j] = 0.f;
        #pragma unroll
        for (int pair = 0; pair < 2; pair++) {
            int be = (gq*32 + pair*16)*40;
            #pragma unroll
            for (int kk = 0; kk < 2; kk++) {
                uint32_t b0, b1, b2, b3;
                uint32_t off = (be + kk*16 + laneK)*2;
                ldsm4(b0, b1, b2, b3, kh_u + off);
                mma16816h(acc[pair*2  ], aq[kk], b0, b1);
                mma16816h(acc[pair*2+1], aq[kk], b2, b3);
            }
        }
        #pragma unroll
        for (int nt = 0; nt < 4; nt++) {
            s0 += ex2(acc[nt][0]) + ex2(acc[nt][1]);
            s1 += ex2(acc[nt][2]) + ex2(acc[nt][3]);
        }
    }
}

__device__ __forceinline__ void qk_group(
        uint32_t kh_u, int laneK, int kbe,
        const uint32_t aq[2][4], float acc[2][4]) {
    #pragma unroll
    for (int i = 0; i < 2; i++)
        #pragma unroll
        for (int j = 0; j < 4; j++) acc[i][j] = 0.f;
    #pragma unroll
    for (int kk = 0; kk < 2; kk++) {
        uint32_t b0, b1, b2, b3;
        uint32_t off = (kbe + kk*16 + laneK)*2;
        ldsm4(b0, b1, b2, b3, kh_u + off);
        mma16816h(acc[0], aq[kk], b0, b1);
        mma16816h(acc[1], aq[kk], b2, b3);
    }
}

// exp, store P (one v4 per row), PV. acc[0]=smem cols fc,fc+1 ; acc[1]=fc+8,+9.
// Thread's global columns: k0+g*16 + 2*fc .. +3 (sigma mapping).
template<bool MASK>
__device__ __forceinline__ void emit_group(
        uint32_t vh_u, int laneV, int g, int k0, int fc,
        float inv0, float inv1,
        float* prow0, float* prow1, bool wr0, bool wr1,
        const float acc[2][4], float oacc[4][4]) {
    int kbe = g*16*40;
    bool ok = !MASK || ((k0 + g*16) < Ld);   // group-aligned mask (Ld % 16 == 0)
    int colb = k0 + g*16 + fc*2;

    // row fr: smem cols (fc,fc+1,fc+8,fc+9) -> global cols colb..colb+3
    float q00 = ok ? ex2(acc[0][0])*inv0 : 0.f;
    float q01 = ok ? ex2(acc[0][1])*inv0 : 0.f;
    float q02 = ok ? ex2(acc[1][0])*inv0 : 0.f;
    float q03 = ok ? ex2(acc[1][1])*inv0 : 0.f;
    // row fr+8
    float q10 = ok ? ex2(acc[0][2])*inv1 : 0.f;
    float q11 = ok ? ex2(acc[0][3])*inv1 : 0.f;
    float q12 = ok ? ex2(acc[1][2])*inv1 : 0.f;
    float q13 = ok ? ex2(acc[1][3])*inv1 : 0.f;

    if (ok) {
        if (wr0) stcs4(&prow0[colb], q00, q01, q02, q03);
        if (wr1) stcs4(&prow1[colb], q10, q11, q12, q13);
    }

    // PV A fragments in smem-column order (matches permuted V)
    uint32_t ah[4];
    ah[0] = pk2h(q00, q01);   // row fr,   smem cols fc,fc+1
    ah[1] = pk2h(q10, q11);   // row fr+8, smem cols fc,fc+1
    ah[2] = pk2h(q02, q03);   // row fr,   smem cols fc+8,fc+9
    ah[3] = pk2h(q12, q13);   // row fr+8, smem cols fc+8,fc+9

    #pragma unroll
    for (int dp = 0; dp < 2; dp++) {
        uint32_t v0, v1, v2, v3;
        uint32_t off = (kbe + dp*16 + laneV)*2;
        ldsm4t(v0, v1, v2, v3, vh_u + off);
        mma16816h(oacc[dp*2  ], ah, v0, v1);
        mma16816h(oacc[dp*2+1], ah, v2, v3);
    }
}

template<bool MASK>
__device__ __forceinline__ void qk_emit_chunk(
        uint32_t kh_u, uint32_t vh_u, int laneK, int laneV,
        const uint32_t aq[2][4],
        int k0, int fc, float inv0, float inv1,
        float* prow0, float* prow1, bool wr0, bool wr1,
        float oacc[4][4]) {
    float aA[2][4], aB[2][4];
    qk_group(kh_u, laneK, 0, aq, aA);
    #pragma unroll
    for (int g = 0; g < 8; g += 2) {
        qk_group(kh_u, laneK, (g+1)*640, aq, aB);
        emit_group<MASK>(vh_u, laneV, g, k0, fc, inv0, inv1,
                         prow0, prow1, wr0, wr1, aA, oacc);
        if (g + 2 < 8)
            qk_group(kh_u, laneK, (g+2)*640, aq, aA);
        emit_group<MASK>(vh_u, laneV, g+1, k0, fc, inv0, inv1,
                         prow0, prow1, wr0, wr1, aB, oacc);
    }
}

__global__ __launch_bounds__(256, 3) void attn_kernel(
        const __half* __restrict__ qkv,
        float* __restrict__ Pout,
        __half* __restrict__ Oh, __half* __restrict__ Ol) {
    extern __shared__ __half smh[];
    uint32_t sm_u = (uint32_t)__cvta_generic_to_shared(smh);

    const int tid = threadIdx.x, lane = tid & 31, warp = tid >> 5;
    const int bh = blockIdx.y;
    const int b  = bh >> 2, h = bh & 3;
    const int q0 = blockIdx.x * QT;
    const size_t base = ((size_t)b*Ld*Hd + h)*DKd;
    const __half* Q = qkv;
    const __half* K = qkv + (size_t)BLd*128;
    const __half* V = qkv + (size_t)2*BLd*128;

    const int mrow = warp * 16;
    const int fr = lane >> 2, fc = (lane & 3) * 2;
    const int lr = lane & 7, sel = lane >> 3;
    const int laneK = ((sel>>1)*8 + lr)*40 + (sel&1)*8;
    const int laneV = ((sel&1)*8 + lr)*40 + (sel>>1)*8;

    const int r0g = q0 + mrow + fr, r1g = r0g + 8;
    const bool q0ok = (r0g < Ld), q1ok = (r1g < Ld);
    uint32_t aq[2][4];
    #pragma unroll
    for (int kk = 0; kk < 2; kk++) {
        int c = kk*16 + fc;
        size_t g0 = base + (size_t)r0g*128 + c;
        size_t g1 = base + (size_t)r1g*128 + c;
        aq[kk][0] = q0ok ? *(const uint32_t*)&Q[g0]     : 0;
        aq[kk][1] = q1ok ? *(const uint32_t*)&Q[g1]     : 0;
        aq[kk][2] = q0ok ? *(const uint32_t*)&Q[g0 + 8] : 0;
        aq[kk][3] = q1ok ? *(const uint32_t*)&Q[g1 + 8] : 0;
    }

    float s0 = 0.f, s1 = 0.f;

    // ======== PASS A: row sums (K only, 4-buffer ring, 2 chunks/sync) ====
    stage1(sm_u, 0*BUFB, 0, K, base, tid);
    stage1(sm_u, 1*BUFB, 1, K, base, tid); cpa_commit();
    stage1(sm_u, 2*BUFB, 2, K, base, tid);
    stage1(sm_u, 3*BUFB, 3, K, base, tid); cpa_commit();
    #pragma unroll 1
    for (int it = 0; it < 8; it++) {
        if (it < 7) cpa_wait<1>(); else cpa_wait<0>();
        __syncthreads();
        int b0 = (it & 1) ? 2 : 0;
        qk_stats_chunk(sm_u + b0*BUFB,     laneK, aq, s0, s1);
        qk_stats_chunk(sm_u + (b0+1)*BUFB, laneK, aq, s0, s1);
        __syncthreads();
        if (it < 6) {
            stage1(sm_u, b0*BUFB,     2*it+4, K, base, tid);
            stage1(sm_u, (b0+1)*BUFB, 2*it+5, K, base, tid);
            cpa_commit();
        }
    }

    // prologue for pass B overlaps the reduction: K in bufs 0/1, V in 2/3
    stage1(sm_u, 0*BUFB, 0, K, base, tid);
    stage1(sm_u, 2*BUFB, 0, V, base, tid); cpa_commit();
    stage1(sm_u, 1*BUFB, 1, K, base, tid);
    stage1(sm_u, 3*BUFB, 1, V, base, tid); cpa_commit();

    s0 += __shfl_xor_sync(~0u, s0, 1);
    s0 += __shfl_xor_sync(~0u, s0, 2);
    s1 += __shfl_xor_sync(~0u, s1, 1);
    s1 += __shfl_xor_sync(~0u, s1, 2);
    s0 -= NPAD;
    s1 -= NPAD;
    const float inv0 = 1.f / s0, inv1 = 1.f / s1;

    // ======== PASS B: P out + PV ========
    float oacc[4][4];
    #pragma unroll
    for (int i = 0; i < 4; i++)
        #pragma unroll
        for (int j = 0; j < 4; j++) oacc[i][j] = 0.f;

    float* prow0 = &Pout[((size_t)bh*Ld + r0g)*Ld];
    float* prow1 = prow0 + 8*(size_t)Ld;

    #pragma unroll 1
    for (int ch = 0; ch < NCH; ch++) {
        if (ch < NCH-1) cpa_wait<1>(); else cpa_wait<0>();
        __syncthreads();
        int buf = ch & 1;
        uint32_t kh_u = sm_u + buf*BUFB;
        uint32_t vh_u = sm_u + (2 + buf)*BUFB;
        if (ch < NCH-1)
            qk_emit_chunk<false>(kh_u, vh_u, laneK, laneV, aq,
                                 ch*KT, fc, inv0, inv1, prow0, prow1, q0ok, q1ok, oacc);
        else
            qk_emit_chunk<true >(kh_u, vh_u, laneK, laneV, aq,
                                 ch*KT, fc, inv0, inv1, prow0, prow1, q0ok, q1ok, oacc);
        __syncthreads();
        if (ch + 2 < NCH) {
            stage1(sm_u, buf*BUFB,       ch+2, K, base, tid);
            stage1(sm_u, (2 + buf)*BUFB, ch+2, V, base, tid);
            cpa_commit();
        }
    }

    // ---- write O (split fp16) ----
    #pragma unroll
    for (int dt = 0; dt < 4; dt++) {
        int d = dt*8 + fc;
        if (q0ok) {
            size_t g = base + (size_t)r0g*128 + d;
            __half hh, ll;
            fsplit_h(oacc[dt][0], hh, ll); Oh[g]   = hh; Ol[g]   = ll;
            fsplit_h(oacc[dt][1], hh, ll); Oh[g+1] = hh; Ol[g+1] = ll;
        }
        if (q1ok) {
            size_t g = base + (size_t)r1g*128 + d;
            __half hh, ll;
            fsplit_h(oacc[dt][2], hh, ll); Oh[g]   = hh; Ol[g]   = ll;
            fsplit_h(oacc[dt][3], hh, ll); Oh[g+1] = hh; Ol[g+1] = ll;
        }
    }
}

// ---------------------------------------------------------------------------
// Final head tail: out = relu_h(g_tmp fp32) @ o2w + o2b   (warp per token)
// ---------------------------------------------------------------------------
__global__ __launch_bounds__(256) void head2_kernel(const float* __restrict__ o2w,
                                                    const float* __restrict__ o2b,
                                                    float* __restrict__ out) {
    int warp = threadIdx.x >> 5, lane = threadIdx.x & 31;
    int token = blockIdx.x * 8 + warp;
    const float* hp = &g_tmp[(size_t)token*Dd];
    float a0 = 0.f, a1 = 0.f;
    #pragma unroll
    for (int j = 0; j < 8; j++) {
        int k = lane + j*32;
        float hv = hp[k];
        a0 = fmaf(hv, o2w[k*2],   a0);
        a1 = fmaf(hv, o2w[k*2+1], a1);
    }
    #pragma unroll
    for (int o = 16; o; o >>= 1) {
        a0 += __shfl_xor_sync(~0u, a0, o);
        a1 += __shfl_xor_sync(~0u, a1, o);
    }
    if (lane == 0) {
        out[(size_t)token*2]     = a0 + o2b[0];
        out[(size_t)token*2 + 1] = a1 + o2b[1];
    }
}

// ---------------------------------------------------------------------------
// Host orchestration
// ---------------------------------------------------------------------------
static inline void* symaddr(const void* s) {
    void* p = nullptr;
    cudaGetSymbolAddress(&p, s);
    return p;
}

extern "C" void kernel_launch(void* const* d_in, const int* in_sizes, int n_in,
                              void* d_out, int out_size) {
    const float* x    = (const float*)d_in[0];
    const float* in_w = (const float*)d_in[1];
    const float* in_b = (const float*)d_in[2];
    const float* qw   = (const float*)d_in[3];
    const float* qb   = (const float*)d_in[4];
    const float* kw   = (const float*)d_in[5];
    const float* kb   = (const float*)d_in[6];
    const float* vw   = (const float*)d_in[7];
    const float* vb   = (const float*)d_in[8];
    const float* ow   = (const float*)d_in[9];
    const float* ob   = (const float*)d_in[10];
    const float* f1w  = (const float*)d_in[11];
    const float* f1b  = (const float*)d_in[12];
    const float* f2w  = (const float*)d_in[13];
    const float* f2b  = (const float*)d_in[14];
    const float* n1g  = (const float*)d_in[15];
    const float* n1b  = (const float*)d_in[16];
    const float* n2g  = (const float*)d_in[17];
    const float* n2b  = (const float*)d_in[18];
    const float* o1w  = (const float*)d_in[19];
    const float* o1b  = (const float*)d_in[20];
    const float* o2w  = (const float*)d_in[21];
    const float* o2b  = (const float*)d_in[22];

    float* outp     = (float*)d_out;
    float* attn_out = outp + (size_t)Bd*Ld*2;

    __half* p_hh   = (__half*)symaddr(g_hh);
    __half* p_hl   = (__half*)symaddr(g_hl);
    __half* p_qkv  = (__half*)symaddr(g_qkv);
    __half* p_oh   = (__half*)symaddr(g_oh);
    __half* p_ol   = (__half*)symaddr(g_ol);
    float*  p_tmp  = (float*)symaddr(g_tmp);
    __half* p_ow   = (__half*)symaddr(g_ow);
    __half* p_f1w  = (__half*)symaddr(g_f1w);
    __half* p_f2w  = (__half*)symaddr(g_f2w);
    __half* p_o1w  = (__half*)symaddr(g_o1w);

    const int SM_QKV  = (2*128 + 128)*(256+8)*2;             // 202752
    const int SM_HEAD = (2*128 + 64)*(256+8)*2;              // 168960

    cudaFuncSetAttribute(gemm_qkv, cudaFuncAttributeMaxDynamicSharedMemorySize, SM_QKV);
    cudaFuncSetAttribute(gemm_bias<256,4,0,true>, cudaFuncAttributeMaxDynamicSharedMemorySize, SM_HEAD);
    cudaFuncSetAttribute(fused_tail, cudaFuncAttributeMaxDynamicSharedMemorySize, SM_TAIL_BYTES);
    cudaFuncSetAttribute(attn_kernel, cudaFuncAttributeMaxDynamicSharedMemorySize, SM_ATTN_BYTES);

    convert_w<<<384, 256>>>(qw, kw, vw, ow, f1w, f2w, o1w, qb, kb, vb);
    embed_kernel<<<BLd, Dd>>>(x, in_w, in_b);

    const dim3 gQKV (BLd/128, 3);
    const dim3 gProj(BLd/128, 4);   // N=256 (head only)
    const dim3 gLN  (BLd/128);
    const dim3 gAttn((Ld + QT - 1)/QT, Bd*Hd);

    for (int i = 0; i < NLd; i++) {
        gemm_qkv<<<gQKV, 512, SM_QKV>>>(i);

        attn_kernel<<<gAttn, 256, SM_ATTN_BYTES>>>(
            p_qkv, attn_out + (size_t)i*Bd*Hd*Ld*Ld, p_oh, p_ol);

        fused_tail<<<gLN, 512, SM_TAIL_BYTES>>>(
            p_oh, p_ol,
            p_ow + (size_t)i*128*Dd, ob + i*Dd,
            n1g + i*Dd, n1b + i*Dd,
            p_f1w + (size_t)i*Dd*FCd, f1b + i*FCd,
            p_f2w + (size_t)i*FCd*Dd, f2b + i*Dd,
            n2g + i*Dd, n2b + i*Dd);
    }

    gemm_bias<256,4,0,true><<<gProj, 512, SM_HEAD>>>(
        p_hh, p_hl, p_o1w, o1b, p_tmp, nullptr, Dd);
    head2_kernel<<<BLd/8, 256>>>(o2w, o2b, outp);
}